// round 2
// baseline (speedup 1.0000x reference)
#include <cuda_runtime.h>
#include <math.h>

#define B_DIM 64
#define I_DIM 32
#define T_DIM 1024
#define H_DIM 512
#define K_PATH 8
#define NPATH 9

#define GRID 148
#define BLK  256
#define GATE_TILES 640   // 10 pairs x 16 h-tiles(32) x 4 b-quarters(16)

// ---------------- scratch (device globals: alloc-free) ----------------
__device__ float g_h[B_DIM * H_DIM];
__device__ float g_c[B_DIM * H_DIM];
__device__ float g_f[B_DIM * H_DIM];
__device__ float g_o[B_DIM * H_DIM];
__device__ float g_l[B_DIM * NPATH * H_DIM];

__device__ unsigned g_bar_count = 0;
__device__ volatile unsigned g_bar_gen = 0;

struct GateArgs {
    const float* Y;
    const float* x[K_PATH];
    const float *W_i, *U_i, *b_i;
    const float *W_f, *U_f, *b_f;
    const float *W_c, *U_c, *b_c;
    const float *W_o, *U_o, *b_o;
    const float *W_i_x, *U_i_x, *b_i_x;
    const float *W_c_x, *U_c_x, *b_c_x;
    const float *W_a, *b_a;
};

__device__ __forceinline__ float sigf(float z) { return 1.0f / (1.0f + expf(-z)); }

__device__ __forceinline__ void grid_barrier()
{
    __syncthreads();
    if (threadIdx.x == 0) {
        __threadfence();
        unsigned gen = g_bar_gen;
        if (atomicAdd(&g_bar_count, 1u) == (unsigned)(gridDim.x - 1)) {
            g_bar_count = 0;
            __threadfence();
            g_bar_gen = gen + 1;
        } else {
            while (g_bar_gen == gen) { __nanosleep(64); }
            __threadfence();
        }
    }
    __syncthreads();
}

// ---------------------------------------------------------------------
__global__ __launch_bounds__(BLK) void lstm_persistent(GateArgs a, float* __restrict__ out,
                                                       int seq_off, int write_hT)
{
    __shared__ float sh_h[16][516];    // 16 b rows x 512 j (+4 pad, bank-conflict free)
    __shared__ float sh_in[16][36];    // staged per-step inputs
    __shared__ float sh_red[128][8];   // z=1 partial accumulators

    const int tid = threadIdx.x;
    const int bid = blockIdx.x;

    // zero h0, c0
    for (int i = bid * BLK + tid; i < B_DIM * H_DIM; i += GRID * BLK) {
        g_h[i] = 0.0f; g_c[i] = 0.0f;
    }
    grid_barrier();

    // thread layout for gate phase
    const int tx = tid & 7;            // 8 groups of 4 consecutive h
    const int ty = (tid >> 3) & 15;    // 16 b rows
    const int z  = tid >> 7;           // j-half (0: j<256, 1: j>=256)

    for (int t = 0; t < T_DIM; t++) {
        // ================= GATE PHASE =================
        for (int tile = bid; tile < GATE_TILES; tile += GRID) {
            const int pair = tile >> 6;
            const int rem  = tile & 63;
            const int h0   = (rem >> 2) * 32;
            const int b0   = (rem & 3) * 16;

            const float *UA, *UB, *bA, *bB, *WA, *WB;
            int inw;
            if (pair == 0)      { UA = a.U_i; bA = a.b_i; WA = a.W_i; UB = a.U_c; bB = a.b_c; WB = a.W_c; inw = I_DIM; }
            else if (pair == 1) { UA = a.U_f; bA = a.b_f; WA = a.W_f; UB = a.U_o; bB = a.b_o; WB = a.W_o; inw = I_DIM; }
            else {
                const int k = pair - 2;
                UA = a.U_i_x + (size_t)k * H_DIM * H_DIM; bA = a.b_i_x + k * H_DIM; WA = a.W_i_x + k * 3 * H_DIM;
                UB = a.U_c_x + (size_t)k * H_DIM * H_DIM; bB = a.b_c_x + k * H_DIM; WB = a.W_c_x + k * 3 * H_DIM;
                inw = 3;
            }

            __syncthreads();   // protect sh_h / sh_red reuse across tiles

            // stage h_prev rows [b0, b0+16)
            for (int e = tid; e < 16 * 128; e += BLK) {
                const int r = e >> 7, q = e & 127;
                float4 v = ((const float4*)g_h)[(size_t)(b0 + r) * (H_DIM / 4) + q];
                sh_h[r][q * 4 + 0] = v.x; sh_h[r][q * 4 + 1] = v.y;
                sh_h[r][q * 4 + 2] = v.z; sh_h[r][q * 4 + 3] = v.w;
            }
            // stage inputs
            if (inw == I_DIM) {
                for (int e = tid; e < 16 * 32; e += BLK) {
                    const int r = e >> 5, i = e & 31;
                    sh_in[r][i] = a.Y[((size_t)(b0 + r) * I_DIM + i) * T_DIM + t];
                }
            } else {
                const int k = pair - 2;
                const float* xa = a.x[(k == 0) ? 0 : 1];
                const float* xb = a.x[k];
                if (tid < 48) {
                    const int r = tid / 3, i = tid % 3;
                    sh_in[r][i]     = xa[((size_t)(b0 + r) * 3 + i) * T_DIM + t];
                    sh_in[r][3 + i] = xb[((size_t)(b0 + r) * 3 + i) * T_DIM + t];
                }
            }
            __syncthreads();

            const int h = h0 + tx * 4;
            float accA[4] = {0.f, 0.f, 0.f, 0.f};
            float accB[4] = {0.f, 0.f, 0.f, 0.f};

            // input projection (split across z)
            if (inw == I_DIM) {
                const int i0 = z * 16;
                #pragma unroll 4
                for (int i = i0; i < i0 + 16; i++) {
                    const float v = sh_in[ty][i];
                    float4 wa = *(const float4*)(WA + (size_t)i * H_DIM + h);
                    float4 wb = *(const float4*)(WB + (size_t)i * H_DIM + h);
                    accA[0] += v * wa.x; accA[1] += v * wa.y; accA[2] += v * wa.z; accA[3] += v * wa.w;
                    accB[0] += v * wb.x; accB[1] += v * wb.y; accB[2] += v * wb.z; accB[3] += v * wb.w;
                }
            } else {
                if (z == 0) {
                    #pragma unroll
                    for (int i = 0; i < 3; i++) {
                        const float v = sh_in[ty][i];
                        float4 wa = *(const float4*)(WA + (size_t)i * H_DIM + h);
                        accA[0] += v * wa.x; accA[1] += v * wa.y; accA[2] += v * wa.z; accA[3] += v * wa.w;
                    }
                } else {
                    #pragma unroll
                    for (int i = 0; i < 3; i++) {
                        const float v = sh_in[ty][3 + i];
                        float4 wb = *(const float4*)(WB + (size_t)i * H_DIM + h);
                        accB[0] += v * wb.x; accB[1] += v * wb.y; accB[2] += v * wb.z; accB[3] += v * wb.w;
                    }
                }
            }

            // recurrent term over this thread's j-half
            {
                const float* pA = UA + h;
                const float* pB = UB + h;
                const int j0 = z * 256;
                #pragma unroll 8
                for (int j = j0; j < j0 + 256; j++) {
                    const float hv = sh_h[ty][j];
                    float4 wa = *(const float4*)(pA + (size_t)j * H_DIM);
                    float4 wb = *(const float4*)(pB + (size_t)j * H_DIM);
                    accA[0] += hv * wa.x; accA[1] += hv * wa.y; accA[2] += hv * wa.z; accA[3] += hv * wa.w;
                    accB[0] += hv * wb.x; accB[1] += hv * wb.y; accB[2] += hv * wb.z; accB[3] += hv * wb.w;
                }
            }

            // reduce z=1 into z=0
            if (z == 1) {
                const int s = tid - 128;
                #pragma unroll
                for (int m = 0; m < 4; m++) { sh_red[s][m] = accA[m]; sh_red[s][4 + m] = accB[m]; }
            }
            __syncthreads();
            if (z == 0) {
                #pragma unroll
                for (int m = 0; m < 4; m++) { accA[m] += sh_red[tid][m]; accB[m] += sh_red[tid][4 + m]; }

                const float4 ba4 = *(const float4*)(bA + h);
                const float4 bb4 = *(const float4*)(bB + h);
                const float bav[4] = {ba4.x, ba4.y, ba4.z, ba4.w};
                const float bbv[4] = {bb4.x, bb4.y, bb4.z, bb4.w};
                const int b = b0 + ty;

                float rA[4], rB[4];
                #pragma unroll
                for (int m = 0; m < 4; m++) {
                    rA[m] = sigf(accA[m] + bav[m]);
                    rB[m] = (pair == 1) ? sigf(accB[m] + bbv[m]) : tanhf(accB[m] + bbv[m]);
                }
                if (pair == 1) {
                    *(float4*)(g_f + (size_t)b * H_DIM + h) = make_float4(rA[0], rA[1], rA[2], rA[3]);
                    *(float4*)(g_o + (size_t)b * H_DIM + h) = make_float4(rB[0], rB[1], rB[2], rB[3]);
                } else {
                    const int kk = (pair == 0) ? 0 : (pair - 1);
                    *(float4*)(g_l + ((size_t)b * NPATH + kk) * H_DIM + h) =
                        make_float4(rA[0] * rB[0], rA[1] * rB[1], rA[2] * rB[2], rA[3] * rB[3]);
                }
            }
        }

        grid_barrier();

        // ================= COMBINE PHASE =================
        if (bid < 128) {
            const int ht = bid >> 3;          // 16 h-tiles of 32
            const int bo = bid & 7;           // 8 b-octets of 8
            const int h = ht * 32 + (tid & 31);
            const int b = bo * 8 + (tid >> 5);

            const float* lb = g_l + (size_t)b * NPATH * H_DIM;
            const float* pw = a.W_a + h;

            float u[NPATH];
            #pragma unroll
            for (int k = 0; k < NPATH; k++) u[k] = 0.0f;

            #pragma unroll 2
            for (int j = 0; j < H_DIM; j += 4) {
                const float w0 = pw[(size_t)(j + 0) * H_DIM];
                const float w1 = pw[(size_t)(j + 1) * H_DIM];
                const float w2 = pw[(size_t)(j + 2) * H_DIM];
                const float w3 = pw[(size_t)(j + 3) * H_DIM];
                #pragma unroll
                for (int k = 0; k < NPATH; k++) {
                    float4 lv = *(const float4*)(lb + (size_t)k * H_DIM + j);
                    u[k] += lv.x * w0 + lv.y * w1 + lv.z * w2 + lv.w * w3;
                }
            }

            const float c_old = g_c[(size_t)b * H_DIM + h];
            const float ba = a.b_a[h];

            float uu[NPATH];
            float mx = -1e30f;
            #pragma unroll
            for (int k = 0; k < NPATH; k++) {
                uu[k] = tanhf(u[k] * c_old + ba);
                mx = fmaxf(mx, uu[k]);
            }
            float se = 0.0f, L = 0.0f;
            #pragma unroll
            for (int k = 0; k < NPATH; k++) {
                const float e = expf(uu[k] - mx);
                se += e;
                L += e * lb[(size_t)k * H_DIM + h];
            }
            L /= se;

            const float cn = g_f[(size_t)b * H_DIM + h] * c_old + L;
            const float hn = g_o[(size_t)b * H_DIM + h] * tanhf(cn);
            g_c[(size_t)b * H_DIM + h] = cn;
            g_h[(size_t)b * H_DIM + h] = hn;

            out[(size_t)seq_off + ((size_t)b * T_DIM + t) * H_DIM + h] = hn;
            if (write_hT && t == T_DIM - 1)
                out[(size_t)b * H_DIM + h] = hn;
        }

        grid_barrier();
    }
}

// ---------------------------------------------------------------------
extern "C" void kernel_launch(void* const* d_in, const int* in_sizes, int n_in,
                              void* d_out, int out_size)
{
    GateArgs a;
    a.Y = (const float*)d_in[0];
    for (int j = 0; j < K_PATH; j++) a.x[j] = (const float*)d_in[1 + j];
    a.W_i   = (const float*)d_in[9];  a.U_i   = (const float*)d_in[10]; a.b_i   = (const float*)d_in[11];
    a.W_f   = (const float*)d_in[12]; a.U_f   = (const float*)d_in[13]; a.b_f   = (const float*)d_in[14];
    a.W_c   = (const float*)d_in[15]; a.U_c   = (const float*)d_in[16]; a.b_c   = (const float*)d_in[17];
    a.W_o   = (const float*)d_in[18]; a.U_o   = (const float*)d_in[19]; a.b_o   = (const float*)d_in[20];
    a.W_i_x = (const float*)d_in[21]; a.U_i_x = (const float*)d_in[22]; a.b_i_x = (const float*)d_in[23];
    a.W_c_x = (const float*)d_in[24]; a.U_c_x = (const float*)d_in[25]; a.b_c_x = (const float*)d_in[26];
    a.W_a   = (const float*)d_in[27]; a.b_a   = (const float*)d_in[28];

    float* out = (float*)d_out;
    const int full = B_DIM * H_DIM + B_DIM * T_DIM * H_DIM;
    const int seq_off = (out_size >= full) ? (B_DIM * H_DIM) : 0;
    const int write_hT = (seq_off != 0) ? 1 : 0;

    lstm_persistent<<<GRID, BLK>>>(a, out, seq_off, write_hT);
}

// round 3
// speedup vs baseline: 2.9583x; 2.9583x over previous
#include <cuda_runtime.h>
#include <math.h>

#define B_DIM 64
#define T_DIM 1024
#define H_DIM 512
#define NPATH 9
#define NMAT  20
#define GRID  148
#define BLK   512
#define SCOLS 72          // padded col slots per block (8 lanes x 9 accs)
#define WPAD  516         // smem row stride for U columns (conflict-free, 16B-aligned)
#define WINP  36          // smem row stride for input-proj weights

// ---- smem layout (floats) ----
#define OFF_W    0
#define OFF_WIN  (SCOLS*WPAD)                 // 37152
#define OFF_BIAS (OFF_WIN + SCOLS*WINP)       // 39744
#define OFF_U    (OFF_BIAS + SCOLS)           // 39816 (16B aligned)
#define UNION_FLOATS 15744                    // max(phaseA 11776, phaseB 15744)
#define SMEM_FLOATS (OFF_U + UNION_FLOATS)    // 55560 -> 222240 bytes

// ---- device scratch ----
__device__ float g_h[B_DIM * H_DIM];
__device__ float g_c[B_DIM * H_DIM];
__device__ float g_act[NMAT * B_DIM * H_DIM];
__device__ unsigned g_bar_count = 0;
__device__ volatile unsigned g_bar_gen = 0;

struct Params {
    const float* U[NMAT];    // 20 recurrent matrices [512x512], column c used
    const float* W[NMAT];    // input projections: m<4 -> [32x512], else [3x512]
    const float* bb[NMAT];   // biases [512]
    const float* Y;          // [B,32,T]
    const float* x[8];       // [B,3,T]
    const float* W_a;        // [512,512]
    const float* b_a;        // [512]
};

__device__ __forceinline__ void grid_barrier()
{
    __syncthreads();
    if (threadIdx.x == 0) {
        __threadfence();
        unsigned gen = g_bar_gen;
        if (atomicAdd(&g_bar_count, 1u) == (unsigned)(gridDim.x - 1)) {
            g_bar_count = 0;
            __threadfence();
            g_bar_gen = gen + 1;
        } else {
            while (g_bar_gen == gen) { __nanosleep(32); }
            __threadfence();
        }
    }
    __syncthreads();
}

extern __shared__ float sm[];

__global__ __launch_bounds__(BLK, 1) void lstm_ws(Params p, float* __restrict__ out,
                                                  int seq_off, int write_hT)
{
    const int tid = threadIdx.x;
    const int bid = blockIdx.x;

    float* w_sm   = sm + OFF_W;
    float* win_sm = sm + OFF_WIN;
    float* bias_sm = sm + OFF_BIAS;
    float* un     = sm + OFF_U;

    // column slice owned by this block: 28 blocks get 70 cols, 120 get 69
    const int start = bid * 69 + min(bid, 28);
    const int cnt   = 69 + (bid < 28 ? 1 : 0);

    // init h0, c0
    for (int i = bid * BLK + tid; i < B_DIM * H_DIM; i += GRID * BLK) {
        g_h[i] = 0.0f; g_c[i] = 0.0f;
    }

    // ---- one-time: load stationary weights into smem ----
    for (int e = tid; e < SCOLS * WPAD; e += BLK) w_sm[e] = 0.0f;
    for (int e = tid; e < SCOLS * WINP; e += BLK) win_sm[e] = 0.0f;
    for (int e = tid; e < SCOLS; e += BLK) bias_sm[e] = 0.0f;
    __syncthreads();
    for (int e = tid; e < cnt * H_DIM; e += BLK) {
        const int s = e >> 9, j = e & 511;
        const int gc = start + s, m = gc >> 9, c = gc & 511;
        w_sm[s * WPAD + j] = p.U[m][(size_t)j * H_DIM + c];
    }
    for (int e = tid; e < cnt * 32; e += BLK) {
        const int s = e >> 5, i = e & 31;
        const int gc = start + s, m = gc >> 9, c = gc & 511;
        const int ni = (m < 4) ? 32 : 3;
        if (i < ni) win_sm[s * WINP + i] = p.W[m][(size_t)i * H_DIM + c];
    }
    for (int s = tid; s < cnt; s += BLK) {
        const int gc = start + s;
        bias_sm[s] = p.bb[gc >> 9][gc & 511];
    }
    grid_barrier();

    // phase A thread roles: 64 b-rows x 8 col-lanes
    const int ab  = tid >> 3;
    const int acs = tid & 7;
    // phase B thread roles: 2 j-halves x 8 b x 32 h
    const int zB = tid >> 8;
    const int bl = (tid >> 5) & 7;
    const int hl = tid & 31;
    const int Bbg = bid >> 4, Bhg = bid & 15;
    const int Bb = Bbg * 8 + bl, Bh = Bhg * 32 + hl;
    const int P = B_DIM * H_DIM;

    for (int t = 0; t < T_DIM; t++) {
        // ================= PHASE A: all 20 gate GEMVs =================
        float* shh = un;              // [64][128] h chunk
        float* shY = un + 8192;       // [64][32]
        float* shx = un + 10240;      // [8][64][3]

        for (int e = tid; e < 2048; e += BLK) {
            const int b2 = e >> 5, i = e & 31;
            shY[e] = p.Y[((size_t)b2 * 32 + i) * T_DIM + t];
        }
        for (int e = tid; e < 1536; e += BLK) {
            const int xk = e / 192, r = e - xk * 192, b2 = r / 3, i = r - b2 * 3;
            shx[e] = p.x[xk][((size_t)b2 * 3 + i) * T_DIM + t];
        }
        __syncthreads();

        float acc[9];
        #pragma unroll
        for (int q = 0; q < 9; q++) {
            const int s = acs + 8 * q;
            const int gc = start + s, m = gc >> 9;
            float a = 0.0f;
            if (m < 4) {
                const float4* yv = (const float4*)(shY + ab * 32);
                const float4* wv = (const float4*)(win_sm + s * WINP);
                #pragma unroll
                for (int i4 = 0; i4 < 8; i4++) {
                    const float4 y = yv[i4], w = wv[i4];
                    a += y.x * w.x + y.y * w.y + y.z * w.z + y.w * w.w;
                }
            } else {
                const int xsel = (m < 12) ? ((m == 4) ? 0 : 1) : min(m - 12, 7);
                const float* xv = shx + (xsel * 64 + ab) * 3;
                const float* wv = win_sm + s * WINP;
                a = xv[0] * wv[0] + xv[1] * wv[1] + xv[2] * wv[2];
            }
            acc[q] = a;
        }

        for (int ch = 0; ch < 4; ch++) {
            __syncthreads();
            for (int e = tid; e < 8192; e += BLK) {
                const int b2 = e >> 7, j = e & 127;
                shh[e] = g_h[b2 * H_DIM + ch * 128 + j];
            }
            __syncthreads();
            const float4* hv4 = (const float4*)(shh + ab * 128);
            const float* wb = w_sm + acs * WPAD + ch * 128;
            #pragma unroll 2
            for (int j4 = 0; j4 < 32; j4++) {
                const float4 h4 = hv4[j4];
                #pragma unroll
                for (int q = 0; q < 9; q++) {
                    const float4 w4 = *(const float4*)(wb + q * (8 * WPAD) + j4 * 4);
                    acc[q] += h4.x * w4.x + h4.y * w4.y + h4.z * w4.z + h4.w * w4.w;
                }
            }
        }

        #pragma unroll
        for (int q = 0; q < 9; q++) {
            const int s = acs + 8 * q;
            if (s < cnt) {
                const int gc = start + s, m = gc >> 9, c = gc & 511;
                const float z = acc[q] + bias_sm[s];
                float r;
                if (m == 2 || m >= 12) r = tanhf(z);
                else                   r = 1.0f / (1.0f + expf(-z));
                g_act[(size_t)m * P + ab * H_DIM + c] = r;
            }
        }
        grid_barrier();

        // ================= PHASE B: W_a GEMM + softmax + state update =================
        if (bid < 128) {
            float* shl = un;           // [8][9][128]
            float* shw = un + 9216;    // [32][132]
            float* shred = un + 13440; // [256][9]

            float u9[9];
            #pragma unroll
            for (int k = 0; k < 9; k++) u9[k] = 0.0f;

            for (int ch = 0; ch < 4; ch++) {
                __syncthreads();
                for (int e = tid; e < 9216; e += BLK) {
                    const int b2 = e / 1152;
                    const int r  = e - b2 * 1152;
                    const int k  = r >> 7, j = r & 127;
                    const int gj = ch * 128 + j;
                    const float* ga = g_act + (size_t)(Bbg * 8 + b2) * H_DIM + gj;
                    float v;
                    if (k == 0) v = ga[0] * ga[2 * (size_t)P];
                    else        v = ga[(size_t)(3 + k) * P] * ga[(size_t)(11 + k) * P];
                    shl[e] = v;
                }
                for (int e = tid; e < 4096; e += BLK) {
                    const int h2 = e & 31, j = e >> 5;
                    shw[h2 * 132 + j] = p.W_a[((size_t)ch * 128 + j) * H_DIM + Bhg * 32 + h2];
                }
                __syncthreads();
                const float4* lr = (const float4*)(shl + bl * 1152 + zB * 64);
                const float4* wr = (const float4*)(shw + hl * 132 + zB * 64);
                #pragma unroll 2
                for (int j4 = 0; j4 < 16; j4++) {
                    const float4 w4 = wr[j4];
                    #pragma unroll
                    for (int k = 0; k < 9; k++) {
                        const float4 l4 = lr[k * 32 + j4];
                        u9[k] += l4.x * w4.x + l4.y * w4.y + l4.z * w4.z + l4.w * w4.w;
                    }
                }
            }

            __syncthreads();
            if (zB == 1) {
                #pragma unroll
                for (int k = 0; k < 9; k++) shred[(tid - 256) * 9 + k] = u9[k];
            }
            __syncthreads();
            if (zB == 0) {
                #pragma unroll
                for (int k = 0; k < 9; k++) u9[k] += shred[tid * 9 + k];

                const float c_old = g_c[Bb * H_DIM + Bh];
                const float ba = p.b_a[Bh];
                const float* ga = g_act + (size_t)Bb * H_DIM + Bh;

                float lv[9];
                lv[0] = ga[0] * ga[2 * (size_t)P];
                #pragma unroll
                for (int k = 1; k < 9; k++)
                    lv[k] = ga[(size_t)(3 + k) * P] * ga[(size_t)(11 + k) * P];

                float uu[9], mx = -1e30f;
                #pragma unroll
                for (int k = 0; k < 9; k++) {
                    uu[k] = tanhf(u9[k] * c_old + ba);
                    mx = fmaxf(mx, uu[k]);
                }
                float se = 0.0f, L = 0.0f;
                #pragma unroll
                for (int k = 0; k < 9; k++) {
                    const float e = expf(uu[k] - mx);
                    se += e;
                    L += e * lv[k];
                }
                L /= se;

                const float cn = ga[1 * (size_t)P] * c_old + L;   // f gate
                const float hn = ga[3 * (size_t)P] * tanhf(cn);   // o gate
                g_c[Bb * H_DIM + Bh] = cn;
                g_h[Bb * H_DIM + Bh] = hn;
                out[(size_t)seq_off + ((size_t)Bb * T_DIM + t) * H_DIM + Bh] = hn;
                if (write_hT && t == T_DIM - 1)
                    out[(size_t)Bb * H_DIM + Bh] = hn;
            }
        }
        grid_barrier();
    }
}

// ---------------------------------------------------------------------
extern "C" void kernel_launch(void* const* d_in, const int* in_sizes, int n_in,
                              void* d_out, int out_size)
{
    Params p;
    p.Y = (const float*)d_in[0];
    for (int j = 0; j < 8; j++) p.x[j] = (const float*)d_in[1 + j];
    const float* W_i = (const float*)d_in[9],  *U_i = (const float*)d_in[10], *b_i = (const float*)d_in[11];
    const float* W_f = (const float*)d_in[12], *U_f = (const float*)d_in[13], *b_f = (const float*)d_in[14];
    const float* W_c = (const float*)d_in[15], *U_c = (const float*)d_in[16], *b_c = (const float*)d_in[17];
    const float* W_o = (const float*)d_in[18], *U_o = (const float*)d_in[19], *b_o = (const float*)d_in[20];
    const float* W_i_x = (const float*)d_in[21], *U_i_x = (const float*)d_in[22], *b_i_x = (const float*)d_in[23];
    const float* W_c_x = (const float*)d_in[24], *U_c_x = (const float*)d_in[25], *b_c_x = (const float*)d_in[26];
    p.W_a = (const float*)d_in[27];
    p.b_a = (const float*)d_in[28];

    // matrix order: 0=i(sig) 1=f(sig) 2=c(tanh) 3=o(sig) 4..11=i_x[k](sig) 12..19=c_x[k](tanh)
    p.U[0] = U_i; p.U[1] = U_f; p.U[2] = U_c; p.U[3] = U_o;
    p.W[0] = W_i; p.W[1] = W_f; p.W[2] = W_c; p.W[3] = W_o;
    p.bb[0] = b_i; p.bb[1] = b_f; p.bb[2] = b_c; p.bb[3] = b_o;
    for (int k = 0; k < 8; k++) {
        p.U[4 + k]  = U_i_x + (size_t)k * H_DIM * H_DIM;
        p.U[12 + k] = U_c_x + (size_t)k * H_DIM * H_DIM;
        p.W[4 + k]  = W_i_x + (size_t)k * 3 * H_DIM;
        p.W[12 + k] = W_c_x + (size_t)k * 3 * H_DIM;
        p.bb[4 + k]  = b_i_x + (size_t)k * H_DIM;
        p.bb[12 + k] = b_c_x + (size_t)k * H_DIM;
    }

    float* out = (float*)d_out;
    const int full = B_DIM * H_DIM + B_DIM * T_DIM * H_DIM;
    const int seq_off = (out_size >= full) ? (B_DIM * H_DIM) : 0;
    const int write_hT = (seq_off != 0) ? 1 : 0;

    static int configured = 0;
    if (!configured) {
        cudaFuncSetAttribute(lstm_ws, cudaFuncAttributeMaxDynamicSharedMemorySize,
                             SMEM_FLOATS * 4);
        configured = 1;
    }
    lstm_ws<<<GRID, BLK, SMEM_FLOATS * 4>>>(p, out, seq_off, write_hT);
}

// round 4
// speedup vs baseline: 2.9599x; 1.0006x over previous
#include <cuda_runtime.h>
#include <math.h>

#define B_DIM 64
#define T_DIM 1024
#define H_DIM 512
#define NPATH 9
#define NMAT  20
#define GRID  148
#define BLK   512
#define SCOLS 72          // padded col slots per block (8 lanes x 9 accs)
#define WPAD  516         // smem row stride for U columns (conflict-free, 16B-aligned)
#define WINP  36          // smem row stride for input-proj weights

// ---- smem layout (floats) ----
#define OFF_W    0
#define OFF_WIN  (SCOLS*WPAD)                 // 37152
#define OFF_BIAS (OFF_WIN + SCOLS*WINP)       // 39744
#define OFF_U    (OFF_BIAS + SCOLS)           // 39816 (16B aligned)
#define UNION_FLOATS 15744                    // max(phaseA 11776, phaseB 15744)
#define SMEM_FLOATS (OFF_U + UNION_FLOATS)    // 55560 -> 222240 bytes

// ---- device scratch ----
__device__ float g_h[B_DIM * H_DIM];
__device__ float g_c[B_DIM * H_DIM];
__device__ float g_act[NMAT * B_DIM * H_DIM];
__device__ unsigned g_bar_count = 0;
__device__ volatile unsigned g_bar_gen = 0;

struct Params {
    const float* U[NMAT];    // 20 recurrent matrices [512x512], column c used
    const float* W[NMAT];    // input projections: m<4 -> [32x512], else [3x512]
    const float* bb[NMAT];   // biases [512]
    const float* Y;          // [B,32,T]
    const float* x[8];       // [B,3,T]
    const float* W_a;        // [512,512]
    const float* b_a;        // [512]
};

__device__ __forceinline__ void grid_barrier()
{
    __syncthreads();
    if (threadIdx.x == 0) {
        __threadfence();
        unsigned gen = g_bar_gen;
        if (atomicAdd(&g_bar_count, 1u) == (unsigned)(gridDim.x - 1)) {
            g_bar_count = 0;
            __threadfence();
            g_bar_gen = gen + 1;
        } else {
            while (g_bar_gen == gen) { __nanosleep(32); }
            __threadfence();
        }
    }
    __syncthreads();
}

extern __shared__ float sm[];

__global__ __launch_bounds__(BLK, 1) void lstm_ws(Params p, float* __restrict__ out,
                                                  int seq_off, int write_hT)
{
    const int tid = threadIdx.x;
    const int bid = blockIdx.x;

    float* w_sm   = sm + OFF_W;
    float* win_sm = sm + OFF_WIN;
    float* bias_sm = sm + OFF_BIAS;
    float* un     = sm + OFF_U;

    // column slice owned by this block: 28 blocks get 70 cols, 120 get 69
    const int start = bid * 69 + min(bid, 28);
    const int cnt   = 69 + (bid < 28 ? 1 : 0);

    // init h0, c0
    for (int i = bid * BLK + tid; i < B_DIM * H_DIM; i += GRID * BLK) {
        g_h[i] = 0.0f; g_c[i] = 0.0f;
    }

    // ---- one-time: load stationary weights into smem ----
    for (int e = tid; e < SCOLS * WPAD; e += BLK) w_sm[e] = 0.0f;
    for (int e = tid; e < SCOLS * WINP; e += BLK) win_sm[e] = 0.0f;
    for (int e = tid; e < SCOLS; e += BLK) bias_sm[e] = 0.0f;
    __syncthreads();
    for (int e = tid; e < cnt * H_DIM; e += BLK) {
        const int s = e >> 9, j = e & 511;
        const int gc = start + s, m = gc >> 9, c = gc & 511;
        w_sm[s * WPAD + j] = p.U[m][(size_t)j * H_DIM + c];
    }
    for (int e = tid; e < cnt * 32; e += BLK) {
        const int s = e >> 5, i = e & 31;
        const int gc = start + s, m = gc >> 9, c = gc & 511;
        const int ni = (m < 4) ? 32 : 3;
        if (i < ni) win_sm[s * WINP + i] = p.W[m][(size_t)i * H_DIM + c];
    }
    for (int s = tid; s < cnt; s += BLK) {
        const int gc = start + s;
        bias_sm[s] = p.bb[gc >> 9][gc & 511];
    }
    grid_barrier();

    // phase A thread roles: 64 b-rows x 8 col-lanes
    const int ab  = tid >> 3;
    const int acs = tid & 7;
    // phase B thread roles: 2 j-halves x 8 b x 32 h
    const int zB = tid >> 8;
    const int bl = (tid >> 5) & 7;
    const int hl = tid & 31;
    const int Bbg = bid >> 4, Bhg = bid & 15;
    const int Bb = Bbg * 8 + bl, Bh = Bhg * 32 + hl;
    const int P = B_DIM * H_DIM;

    for (int t = 0; t < T_DIM; t++) {
        // ================= PHASE A: all 20 gate GEMVs =================
        float* shh = un;              // [64][128] h chunk
        float* shY = un + 8192;       // [64][32]
        float* shx = un + 10240;      // [8][64][3]

        for (int e = tid; e < 2048; e += BLK) {
            const int b2 = e >> 5, i = e & 31;
            shY[e] = p.Y[((size_t)b2 * 32 + i) * T_DIM + t];
        }
        for (int e = tid; e < 1536; e += BLK) {
            const int xk = e / 192, r = e - xk * 192, b2 = r / 3, i = r - b2 * 3;
            shx[e] = p.x[xk][((size_t)b2 * 3 + i) * T_DIM + t];
        }
        __syncthreads();

        float acc[9];
        #pragma unroll
        for (int q = 0; q < 9; q++) {
            const int s = acs + 8 * q;
            const int gc = start + s, m = gc >> 9;
            float a = 0.0f;
            if (m < 4) {
                const float4* yv = (const float4*)(shY + ab * 32);
                const float4* wv = (const float4*)(win_sm + s * WINP);
                #pragma unroll
                for (int i4 = 0; i4 < 8; i4++) {
                    const float4 y = yv[i4], w = wv[i4];
                    a += y.x * w.x + y.y * w.y + y.z * w.z + y.w * w.w;
                }
            } else {
                const int xsel = (m < 12) ? ((m == 4) ? 0 : 1) : min(m - 12, 7);
                const float* xv = shx + (xsel * 64 + ab) * 3;
                const float* wv = win_sm + s * WINP;
                a = xv[0] * wv[0] + xv[1] * wv[1] + xv[2] * wv[2];
            }
            acc[q] = a;
        }

        for (int ch = 0; ch < 4; ch++) {
            __syncthreads();
            for (int e = tid; e < 8192; e += BLK) {
                const int b2 = e >> 7, j = e & 127;
                shh[e] = g_h[b2 * H_DIM + ch * 128 + j];
            }
            __syncthreads();
            const float4* hv4 = (const float4*)(shh + ab * 128);
            const float* wb = w_sm + acs * WPAD + ch * 128;
            #pragma unroll 2
            for (int j4 = 0; j4 < 32; j4++) {
                const float4 h4 = hv4[j4];
                #pragma unroll
                for (int q = 0; q < 9; q++) {
                    const float4 w4 = *(const float4*)(wb + q * (8 * WPAD) + j4 * 4);
                    acc[q] += h4.x * w4.x + h4.y * w4.y + h4.z * w4.z + h4.w * w4.w;
                }
            }
        }

        #pragma unroll
        for (int q = 0; q < 9; q++) {
            const int s = acs + 8 * q;
            if (s < cnt) {
                const int gc = start + s, m = gc >> 9, c = gc & 511;
                const float z = acc[q] + bias_sm[s];
                float r;
                if (m == 2 || m >= 12) r = tanhf(z);
                else                   r = 1.0f / (1.0f + expf(-z));
                g_act[(size_t)m * P + ab * H_DIM + c] = r;
            }
        }
        grid_barrier();

        // ================= PHASE B: W_a GEMM + softmax + state update =================
        if (bid < 128) {
            float* shl = un;           // [8][9][128]
            float* shw = un + 9216;    // [32][132]
            float* shred = un + 13440; // [256][9]

            float u9[9];
            #pragma unroll
            for (int k = 0; k < 9; k++) u9[k] = 0.0f;

            for (int ch = 0; ch < 4; ch++) {
                __syncthreads();
                for (int e = tid; e < 9216; e += BLK) {
                    const int b2 = e / 1152;
                    const int r  = e - b2 * 1152;
                    const int k  = r >> 7, j = r & 127;
                    const int gj = ch * 128 + j;
                    const float* ga = g_act + (size_t)(Bbg * 8 + b2) * H_DIM + gj;
                    float v;
                    if (k == 0) v = ga[0] * ga[2 * (size_t)P];
                    else        v = ga[(size_t)(3 + k) * P] * ga[(size_t)(11 + k) * P];
                    shl[e] = v;
                }
                for (int e = tid; e < 4096; e += BLK) {
                    const int h2 = e & 31, j = e >> 5;
                    shw[h2 * 132 + j] = p.W_a[((size_t)ch * 128 + j) * H_DIM + Bhg * 32 + h2];
                }
                __syncthreads();
                const float4* lr = (const float4*)(shl + bl * 1152 + zB * 64);
                const float4* wr = (const float4*)(shw + hl * 132 + zB * 64);
                #pragma unroll 2
                for (int j4 = 0; j4 < 16; j4++) {
                    const float4 w4 = wr[j4];
                    #pragma unroll
                    for (int k = 0; k < 9; k++) {
                        const float4 l4 = lr[k * 32 + j4];
                        u9[k] += l4.x * w4.x + l4.y * w4.y + l4.z * w4.z + l4.w * w4.w;
                    }
                }
            }

            __syncthreads();
            if (zB == 1) {
                #pragma unroll
                for (int k = 0; k < 9; k++) shred[(tid - 256) * 9 + k] = u9[k];
            }
            __syncthreads();
            if (zB == 0) {
                #pragma unroll
                for (int k = 0; k < 9; k++) u9[k] += shred[tid * 9 + k];

                const float c_old = g_c[Bb * H_DIM + Bh];
                const float ba = p.b_a[Bh];
                const float* ga = g_act + (size_t)Bb * H_DIM + Bh;

                float lv[9];
                lv[0] = ga[0] * ga[2 * (size_t)P];
                #pragma unroll
                for (int k = 1; k < 9; k++)
                    lv[k] = ga[(size_t)(3 + k) * P] * ga[(size_t)(11 + k) * P];

                float uu[9], mx = -1e30f;
                #pragma unroll
                for (int k = 0; k < 9; k++) {
                    uu[k] = tanhf(u9[k] * c_old + ba);
                    mx = fmaxf(mx, uu[k]);
                }
                float se = 0.0f, L = 0.0f;
                #pragma unroll
                for (int k = 0; k < 9; k++) {
                    const float e = expf(uu[k] - mx);
                    se += e;
                    L += e * lv[k];
                }
                L /= se;

                const float cn = ga[1 * (size_t)P] * c_old + L;   // f gate
                const float hn = ga[3 * (size_t)P] * tanhf(cn);   // o gate
                g_c[Bb * H_DIM + Bh] = cn;
                g_h[Bb * H_DIM + Bh] = hn;
                out[(size_t)seq_off + ((size_t)Bb * T_DIM + t) * H_DIM + Bh] = hn;
                if (write_hT && t == T_DIM - 1)
                    out[(size_t)Bb * H_DIM + Bh] = hn;
            }
        }
        grid_barrier();
    }
}

// ---------------------------------------------------------------------
extern "C" void kernel_launch(void* const* d_in, const int* in_sizes, int n_in,
                              void* d_out, int out_size)
{
    Params p;
    p.Y = (const float*)d_in[0];
    for (int j = 0; j < 8; j++) p.x[j] = (const float*)d_in[1 + j];
    const float* W_i = (const float*)d_in[9],  *U_i = (const float*)d_in[10], *b_i = (const float*)d_in[11];
    const float* W_f = (const float*)d_in[12], *U_f = (const float*)d_in[13], *b_f = (const float*)d_in[14];
    const float* W_c = (const float*)d_in[15], *U_c = (const float*)d_in[16], *b_c = (const float*)d_in[17];
    const float* W_o = (const float*)d_in[18], *U_o = (const float*)d_in[19], *b_o = (const float*)d_in[20];
    const float* W_i_x = (const float*)d_in[21], *U_i_x = (const float*)d_in[22], *b_i_x = (const float*)d_in[23];
    const float* W_c_x = (const float*)d_in[24], *U_c_x = (const float*)d_in[25], *b_c_x = (const float*)d_in[26];
    p.W_a = (const float*)d_in[27];
    p.b_a = (const float*)d_in[28];

    // matrix order: 0=i(sig) 1=f(sig) 2=c(tanh) 3=o(sig) 4..11=i_x[k](sig) 12..19=c_x[k](tanh)
    p.U[0] = U_i; p.U[1] = U_f; p.U[2] = U_c; p.U[3] = U_o;
    p.W[0] = W_i; p.W[1] = W_f; p.W[2] = W_c; p.W[3] = W_o;
    p.bb[0] = b_i; p.bb[1] = b_f; p.bb[2] = b_c; p.bb[3] = b_o;
    for (int k = 0; k < 8; k++) {
        p.U[4 + k]  = U_i_x + (size_t)k * H_DIM * H_DIM;
        p.U[12 + k] = U_c_x + (size_t)k * H_DIM * H_DIM;
        p.W[4 + k]  = W_i_x + (size_t)k * 3 * H_DIM;
        p.W[12 + k] = W_c_x + (size_t)k * 3 * H_DIM;
        p.bb[4 + k]  = b_i_x + (size_t)k * H_DIM;
        p.bb[12 + k] = b_c_x + (size_t)k * H_DIM;
    }

    float* out = (float*)d_out;
    const int full = B_DIM * H_DIM + B_DIM * T_DIM * H_DIM;
    const int seq_off = (out_size >= full) ? (B_DIM * H_DIM) : 0;
    const int write_hT = (seq_off != 0) ? 1 : 0;

    static int configured = 0;
    if (!configured) {
        cudaFuncSetAttribute(lstm_ws, cudaFuncAttributeMaxDynamicSharedMemorySize,
                             SMEM_FLOATS * 4);
        configured = 1;
    }
    lstm_ws<<<GRID, BLK, SMEM_FLOATS * 4>>>(p, out, seq_off, write_hT);
}

// round 5
// speedup vs baseline: 3.5365x; 1.1948x over previous
#include <cuda_runtime.h>
#include <math.h>

#define B_DIM 64
#define T_DIM 1024
#define H_DIM 512
#define NMAT  20
#define GRID  128
#define BLK   512
#define NCOL  80          // gate columns per block (128 x 80 = 10240)
#define WPAD  516         // smem row stride for U columns
#define WINP  36          // smem row stride for input-proj weights

// ---- smem layout (float offsets) ----
#define OFF_W    0
#define OFF_WIN  (NCOL*WPAD)             // 41280
#define OFF_BIAS (OFF_WIN + NCOL*WINP)   // 44160
#define OFF_UN   (OFF_BIAS + NCOL)       // 44240 (16B aligned)
#define UN_SZ    9088                    // max(phaseA 7680, phaseB 9088)
#define SMEM_FLOATS (OFF_UN + UN_SZ)     // 53328 floats = 213312 bytes

// ---- device scratch ----
__device__ float g_h[B_DIM * H_DIM];
__device__ float g_c[B_DIM * H_DIM];
__device__ float g_act[NMAT * B_DIM * H_DIM];
__device__ unsigned g_bar_count = 0;
__device__ volatile unsigned g_bar_gen = 0;

struct Params {
    const float* U[NMAT];    // 20 recurrent matrices [512x512]
    const float* W[NMAT];    // input projections: m<4 -> [32x512], else [3x512]
    const float* bb[NMAT];   // biases [512]
    const float* Y;          // [B,32,T]
    const float* x[8];       // [B,3,T]
    const float* W_a;        // [512,512]
    const float* b_a;        // [512]
};

__device__ __forceinline__ float sigf(float z) { return 1.0f / (1.0f + expf(-z)); }

__device__ __forceinline__ void grid_barrier()
{
    __syncthreads();
    if (threadIdx.x == 0) {
        __threadfence();
        unsigned gen = g_bar_gen;
        if (atomicAdd(&g_bar_count, 1u) == (unsigned)(gridDim.x - 1)) {
            g_bar_count = 0;
            __threadfence();
            g_bar_gen = gen + 1;
        } else {
            while (g_bar_gen == gen) { __nanosleep(32); }
            __threadfence();
        }
    }
    __syncthreads();
}

extern __shared__ float sm[];

__global__ __launch_bounds__(BLK, 1) void lstm_ws2(Params p, float* __restrict__ out,
                                                   int seq_off, int write_hT)
{
    const int tid = threadIdx.x;
    const int bid = blockIdx.x;
    const int P = B_DIM * H_DIM;

    float* w_sm  = sm + OFF_W;
    float* win   = sm + OFF_WIN;
    float* bias  = sm + OFF_BIAS;
    float* un    = sm + OFF_UN;

    // init h0, c0
    for (int i = bid * BLK + tid; i < B_DIM * H_DIM; i += GRID * BLK) {
        g_h[i] = 0.0f; g_c[i] = 0.0f;
    }

    // ---- one-time: stationary weights -> smem ----
    for (int e = tid; e < NCOL * WINP; e += BLK) win[e] = 0.0f;
    __syncthreads();
    for (int e = tid; e < NCOL * H_DIM; e += BLK) {
        const int s = e >> 9, j = e & 511;
        const int gc = bid * NCOL + s, m = gc >> 9, c = gc & 511;
        w_sm[s * WPAD + j] = p.U[m][(size_t)j * H_DIM + c];
    }
    for (int e = tid; e < NCOL * 32; e += BLK) {
        const int s = e >> 5, i = e & 31;
        const int gc = bid * NCOL + s, m = gc >> 9, c = gc & 511;
        const int ni = (m < 4) ? 32 : 3;
        if (i < ni) win[s * WINP + i] = p.W[m][(size_t)i * H_DIM + c];
    }
    for (int s = tid; s < NCOL; s += BLK) {
        const int gc = bid * NCOL + s;
        bias[s] = p.bb[gc >> 9][gc & 511];
    }
    grid_barrier();

    // phase A roles: 16 col-lanes x 32 b-lanes (each: 5 cols x 2 b-rows)
    const int cs = tid & 15;
    const int bq = tid >> 4;
    // phase B roles: 2 j-halves x 8 b x 32 h
    const int zB = tid >> 8;
    const int bl = (tid >> 5) & 7;
    const int hl = tid & 31;
    const int Bbg = bid >> 4, Bhg = bid & 15;
    const int Bb = Bbg * 8 + bl, Bh = Bhg * 32 + hl;

    for (int t = 0; t < T_DIM; t++) {
        // ================= PHASE A: 20 gate GEMVs =================
        float* shh = un;              // [64][64] h chunk
        float* shY = un + 4096;       // [64][32]
        float* shx = un + 6144;       // [8][64][3]

        for (int e = tid; e < 2048; e += BLK) {
            const int b2 = e >> 5, i = e & 31;
            shY[e] = p.Y[((size_t)b2 * 32 + i) * T_DIM + t];
        }
        for (int e = tid; e < 1536; e += BLK) {
            const int xk = e / 192, r = e - xk * 192, b2 = r / 3, i = r - b2 * 3;
            shx[e] = p.x[xk][((size_t)b2 * 3 + i) * T_DIM + t];
        }
        __syncthreads();

        float acc0[5], acc1[5];
        #pragma unroll
        for (int q = 0; q < 5; q++) {
            const int s = cs + 16 * q;
            const int gc = bid * NCOL + s, m = gc >> 9;
            float a0 = 0.0f, a1 = 0.0f;
            if (m < 4) {
                const float4* y0 = (const float4*)(shY + bq * 32);
                const float4* y1 = (const float4*)(shY + (bq + 32) * 32);
                const float4* wv = (const float4*)(win + s * WINP);
                #pragma unroll
                for (int i4 = 0; i4 < 8; i4++) {
                    const float4 w = wv[i4], ya = y0[i4], yb = y1[i4];
                    a0 += ya.x * w.x + ya.y * w.y + ya.z * w.z + ya.w * w.w;
                    a1 += yb.x * w.x + yb.y * w.y + yb.z * w.z + yb.w * w.w;
                }
            } else {
                const int k = (m < 12) ? (m - 4) : (m - 12);
                const int xsel = (m < 12) ? ((k == 0) ? 0 : 1) : k;
                const float* xv0 = shx + (xsel * 64 + bq) * 3;
                const float* xv1 = shx + (xsel * 64 + bq + 32) * 3;
                const float* wv = win + s * WINP;
                a0 = xv0[0] * wv[0] + xv0[1] * wv[1] + xv0[2] * wv[2];
                a1 = xv1[0] * wv[0] + xv1[1] * wv[1] + xv1[2] * wv[2];
            }
            acc0[q] = a0; acc1[q] = a1;
        }

        for (int ch = 0; ch < 8; ch++) {
            __syncthreads();
            for (int e = tid; e < 4096; e += BLK) {
                const int b2 = e >> 6, j = e & 63;
                shh[e] = g_h[b2 * H_DIM + ch * 64 + j];
            }
            __syncthreads();
            const float4* h0p = (const float4*)(shh + bq * 64);
            const float4* h1p = (const float4*)(shh + (bq + 32) * 64);
            const float* wb = w_sm + cs * WPAD + ch * 64;
            #pragma unroll 4
            for (int j4 = 0; j4 < 16; j4++) {
                const float4 h0 = h0p[j4];
                const float4 h1 = h1p[j4];
                #pragma unroll
                for (int q = 0; q < 5; q++) {
                    const float4 w = *(const float4*)(wb + q * (16 * WPAD) + j4 * 4);
                    acc0[q] += h0.x * w.x + h0.y * w.y + h0.z * w.z + h0.w * w.w;
                    acc1[q] += h1.x * w.x + h1.y * w.y + h1.z * w.z + h1.w * w.w;
                }
            }
        }

        #pragma unroll
        for (int q = 0; q < 5; q++) {
            const int s = cs + 16 * q;
            const int gc = bid * NCOL + s, m = gc >> 9, c = gc & 511;
            const float bz = bias[s];
            const float z0 = acc0[q] + bz, z1 = acc1[q] + bz;
            float r0, r1;
            if (m == 2 || m >= 12) { r0 = tanhf(z0); r1 = tanhf(z1); }
            else                   { r0 = sigf(z0);  r1 = sigf(z1);  }
            g_act[(size_t)m * P + (size_t)bq * H_DIM + c] = r0;
            g_act[(size_t)m * P + (size_t)(bq + 32) * H_DIM + c] = r1;
        }
        grid_barrier();

        // ================= PHASE B: W_a GEMM + softmax + update =================
        {
            float* shl = un;           // [8 b][9 k][64 j]
            float* shw = un + 4608;    // [32 h][68]
            float* shred = un + 6784;  // [256][9]

            float u9[9];
            #pragma unroll
            for (int k = 0; k < 9; k++) u9[k] = 0.0f;

            for (int ch = 0; ch < 8; ch++) {
                __syncthreads();
                for (int e = tid; e < 4608; e += BLK) {
                    const int b2 = e / 576;
                    const int r  = e - b2 * 576;
                    const int k  = r >> 6, j = r & 63;
                    const int gj = ch * 64 + j;
                    const float* ga = g_act + (size_t)(Bbg * 8 + b2) * H_DIM + gj;
                    float v;
                    if (k == 0) v = ga[0] * ga[2 * (size_t)P];
                    else        v = ga[(size_t)(3 + k) * P] * ga[(size_t)(11 + k) * P];
                    shl[e] = v;
                }
                for (int e = tid; e < 2048; e += BLK) {
                    const int h2 = e & 31, j = e >> 5;
                    shw[h2 * 68 + j] = p.W_a[((size_t)ch * 64 + j) * H_DIM + Bhg * 32 + h2];
                }
                __syncthreads();
                const float4* lr = (const float4*)(shl + bl * 576 + zB * 32);
                const float4* wr = (const float4*)(shw + hl * 68 + zB * 32);
                #pragma unroll
                for (int j4 = 0; j4 < 8; j4++) {
                    const float4 w4 = wr[j4];
                    #pragma unroll
                    for (int k = 0; k < 9; k++) {
                        const float4 l4 = lr[k * 16 + j4];
                        u9[k] += l4.x * w4.x + l4.y * w4.y + l4.z * w4.z + l4.w * w4.w;
                    }
                }
            }

            __syncthreads();
            if (zB == 1) {
                #pragma unroll
                for (int k = 0; k < 9; k++) shred[(tid - 256) * 9 + k] = u9[k];
            }
            __syncthreads();
            if (zB == 0) {
                #pragma unroll
                for (int k = 0; k < 9; k++) u9[k] += shred[tid * 9 + k];

                const float c_old = g_c[Bb * H_DIM + Bh];
                const float ba = p.b_a[Bh];
                const float* ga = g_act + (size_t)Bb * H_DIM + Bh;

                float lv[9];
                lv[0] = ga[0] * ga[2 * (size_t)P];
                #pragma unroll
                for (int k = 1; k < 9; k++)
                    lv[k] = ga[(size_t)(3 + k) * P] * ga[(size_t)(11 + k) * P];

                float uu[9], mx = -1e30f;
                #pragma unroll
                for (int k = 0; k < 9; k++) {
                    uu[k] = tanhf(u9[k] * c_old + ba);
                    mx = fmaxf(mx, uu[k]);
                }
                float se = 0.0f, L = 0.0f;
                #pragma unroll
                for (int k = 0; k < 9; k++) {
                    const float e = expf(uu[k] - mx);
                    se += e;
                    L += e * lv[k];
                }
                L /= se;

                const float cn = ga[1 * (size_t)P] * c_old + L;
                const float hn = ga[3 * (size_t)P] * tanhf(cn);
                g_c[Bb * H_DIM + Bh] = cn;
                g_h[Bb * H_DIM + Bh] = hn;
                out[(size_t)seq_off + ((size_t)Bb * T_DIM + t) * H_DIM + Bh] = hn;
                if (write_hT && t == T_DIM - 1)
                    out[(size_t)Bb * H_DIM + Bh] = hn;
            }
        }
        grid_barrier();
    }
}

// ---------------------------------------------------------------------
extern "C" void kernel_launch(void* const* d_in, const int* in_sizes, int n_in,
                              void* d_out, int out_size)
{
    Params p;
    p.Y = (const float*)d_in[0];
    for (int j = 0; j < 8; j++) p.x[j] = (const float*)d_in[1 + j];
    const float* W_i = (const float*)d_in[9],  *U_i = (const float*)d_in[10], *b_i = (const float*)d_in[11];
    const float* W_f = (const float*)d_in[12], *U_f = (const float*)d_in[13], *b_f = (const float*)d_in[14];
    const float* W_c = (const float*)d_in[15], *U_c = (const float*)d_in[16], *b_c = (const float*)d_in[17];
    const float* W_o = (const float*)d_in[18], *U_o = (const float*)d_in[19], *b_o = (const float*)d_in[20];
    const float* W_i_x = (const float*)d_in[21], *U_i_x = (const float*)d_in[22], *b_i_x = (const float*)d_in[23];
    const float* W_c_x = (const float*)d_in[24], *U_c_x = (const float*)d_in[25], *b_c_x = (const float*)d_in[26];
    p.W_a = (const float*)d_in[27];
    p.b_a = (const float*)d_in[28];

    // order: 0=i(sig) 1=f(sig) 2=c(tanh) 3=o(sig) 4..11=i_x(sig) 12..19=c_x(tanh)
    p.U[0] = U_i; p.U[1] = U_f; p.U[2] = U_c; p.U[3] = U_o;
    p.W[0] = W_i; p.W[1] = W_f; p.W[2] = W_c; p.W[3] = W_o;
    p.bb[0] = b_i; p.bb[1] = b_f; p.bb[2] = b_c; p.bb[3] = b_o;
    for (int k = 0; k < 8; k++) {
        p.U[4 + k]  = U_i_x + (size_t)k * H_DIM * H_DIM;
        p.U[12 + k] = U_c_x + (size_t)k * H_DIM * H_DIM;
        p.W[4 + k]  = W_i_x + (size_t)k * 3 * H_DIM;
        p.W[12 + k] = W_c_x + (size_t)k * 3 * H_DIM;
        p.bb[4 + k]  = b_i_x + (size_t)k * H_DIM;
        p.bb[12 + k] = b_c_x + (size_t)k * H_DIM;
    }

    float* out = (float*)d_out;
    const int full = B_DIM * H_DIM + B_DIM * T_DIM * H_DIM;
    const int seq_off = (out_size >= full) ? (B_DIM * H_DIM) : 0;
    const int write_hT = (seq_off != 0) ? 1 : 0;

    static int configured = 0;
    if (!configured) {
        cudaFuncSetAttribute(lstm_ws2, cudaFuncAttributeMaxDynamicSharedMemorySize,
                             SMEM_FLOATS * 4);
        configured = 1;
    }
    lstm_ws2<<<GRID, BLK, SMEM_FLOATS * 4>>>(p, out, seq_off, write_hT);
}

// round 7
// speedup vs baseline: 4.8374x; 1.3678x over previous
#include <cuda_runtime.h>
#include <cuda_bf16.h>
#include <math.h>
#include <stdint.h>

#define B_DIM 64
#define T_DIM 1024
#define H_DIM 512
#define NMAT  20
#define GRID  128
#define BLK   512
#define NCOL  80
#define P_SZ  (B_DIM * H_DIM)

// ---- smem byte offsets ----
#define BF_B    0          // B frags (U weights) hi/lo: 2 x 80KB
#define BEXT_B  163840     // B-ext frags (input proj) hi/lo: 2 x 10KB
#define BIAS_B  184320     // 80 floats
#define UN_B    184640     // union: A-frags (33792B) / phase-B scratch (36352B)
#define SMEM_BYTES 220992

// A-frag strides (bytes): [prec][mi 4][ks 8][reg 4][lane 32] uint32
#define AF_PREC 16896
#define AF_MI   4224
#define AF_KS   528        // padded (528/4 % 32 = 4) to avoid STS bank conflicts
#define AF_REG  128

// ---- device scratch ----
__device__ float g_h[B_DIM * H_DIM];
__device__ float g_c[B_DIM * H_DIM];
__device__ float g_act[NMAT * B_DIM * H_DIM];
__device__ unsigned g_bar_count = 0;
__device__ volatile unsigned g_bar_gen = 0;

struct Params {
    const float* U[NMAT];
    const float* W[NMAT];
    const float* bb[NMAT];
    const float* Y;
    const float* x[8];
    const float* W_a;
    const float* b_a;
};

__device__ __forceinline__ float sigf(float z) { return 1.0f / (1.0f + expf(-z)); }

__device__ __forceinline__ void cvt_pair(float v0, float v1, uint32_t& hi, uint32_t& lo)
{
    const __nv_bfloat16 h0 = __float2bfloat16(v0), h1 = __float2bfloat16(v1);
    const __nv_bfloat16 l0 = __float2bfloat16(v0 - __bfloat162float(h0));
    const __nv_bfloat16 l1 = __float2bfloat16(v1 - __bfloat162float(h1));
    hi = ((uint32_t)__bfloat16_as_ushort(h1) << 16) | __bfloat16_as_ushort(h0);
    lo = ((uint32_t)__bfloat16_as_ushort(l1) << 16) | __bfloat16_as_ushort(l0);
}

__device__ __forceinline__ void mma16816(float* d, const uint32_t* a, uint32_t b0, uint32_t b1)
{
    asm volatile(
        "mma.sync.aligned.m16n8k16.row.col.f32.bf16.bf16.f32 "
        "{%0,%1,%2,%3}, {%4,%5,%6,%7}, {%8,%9}, {%0,%1,%2,%3};"
        : "+f"(d[0]), "+f"(d[1]), "+f"(d[2]), "+f"(d[3])
        : "r"(a[0]), "r"(a[1]), "r"(a[2]), "r"(a[3]), "r"(b0), "r"(b1));
}

__device__ __forceinline__ void grid_barrier()
{
    __syncthreads();
    if (threadIdx.x == 0) {
        __threadfence();
        unsigned gen = g_bar_gen;
        if (atomicAdd(&g_bar_count, 1u) == (unsigned)(gridDim.x - 1)) {
            g_bar_count = 0;
            __threadfence();
            g_bar_gen = gen + 1;
        } else {
            while (g_bar_gen == gen) { __nanosleep(32); }
            __threadfence();
        }
    }
    __syncthreads();
}

extern __shared__ float sm[];

__global__ __launch_bounds__(BLK, 1) void lstm_mma(Params p, float* __restrict__ out,
                                                   int seq_off, int write_hT)
{
    const int tid = threadIdx.x;
    const int bid = blockIdx.x;
    const int lane = tid & 31;
    const int wid = tid >> 5;
    char* smc = (char*)sm;
    float* bias_sm = (float*)(smc + BIAS_B);
    float* un = (float*)(smc + UN_B);

    // init h0, c0
    for (int i = bid * BLK + tid; i < B_DIM * H_DIM; i += GRID * BLK) {
        g_h[i] = 0.0f; g_c[i] = 0.0f;
    }

    // ---- one-time: U weights -> bf16 hi/lo B-fragments in smem ----
    // B frag (m16n8k16 .col): lane = (n&7)*4 + ((k&7)>>1), reg = (k&15)>>3, half16 = k&1
    for (int e = tid; e < NCOL * H_DIM; e += BLK) {
        const int s = e >> 9, j = e & 511;
        const int gc = bid * NCOL + s, m = gc >> 9, c = gc & 511;
        const float v = p.U[m][(size_t)j * H_DIM + c];
        uint32_t hi, lo; cvt_pair(v, 0.0f, hi, lo);
        const int nt = s >> 3;
        const uint32_t off = (uint32_t)nt * 8192u + (uint32_t)(j >> 4) * 256u
                           + (uint32_t)((s & 7) * 4 + ((j & 7) >> 1)) * 8u
                           + (uint32_t)((j & 15) >> 3) * 4u + (uint32_t)(j & 1) * 2u;
        *(unsigned short*)(smc + BF_B + off)         = (unsigned short)(hi & 0xFFFF);
        *(unsigned short*)(smc + BF_B + 81920 + off) = (unsigned short)(lo & 0xFFFF);
    }
    // ext B frags: zero then fill (q = 0..31: Y rows; 32+xsel*3+i: x rows; rest 0)
    for (int e = tid; e < 5120; e += BLK) ((uint32_t*)(smc + BEXT_B))[e] = 0u;
    __syncthreads();
    for (int e = tid; e < NCOL * 32; e += BLK) {
        const int s = e >> 5, i = e & 31;
        const int gc = bid * NCOL + s, m = gc >> 9, c = gc & 511;
        float v; int q;
        if (m < 4) { v = p.W[m][(size_t)i * H_DIM + c]; q = i; }
        else {
            if (i >= 3) continue;
            const int xsel = (m < 12) ? ((m == 4) ? 0 : 1) : (m - 12);
            v = p.W[m][(size_t)i * H_DIM + c];
            q = 32 + xsel * 3 + i;
        }
        uint32_t hi, lo; cvt_pair(v, 0.0f, hi, lo);
        const int nt = s >> 3;
        const uint32_t off = (uint32_t)nt * 1024u + (uint32_t)(q >> 4) * 256u
                           + (uint32_t)((s & 7) * 4 + ((q & 7) >> 1)) * 8u
                           + (uint32_t)((q & 15) >> 3) * 4u + (uint32_t)(q & 1) * 2u;
        *(unsigned short*)(smc + BEXT_B + off)         = (unsigned short)(hi & 0xFFFF);
        *(unsigned short*)(smc + BEXT_B + 10240 + off) = (unsigned short)(lo & 0xFFFF);
    }
    for (int s = tid; s < NCOL; s += BLK) {
        const int gc = bid * NCOL + s;
        bias_sm[s] = p.bb[gc >> 9][gc & 511];
    }
    grid_barrier();

    // phase A mma roles: warp = (mi, nslot); wid&3 = mi keeps SMSPs balanced
    const int mi = wid & 3;
    const int nslot = wid >> 2;
    const int nt0 = (nslot == 0) ? 0 : (nslot == 1) ? 3 : (nslot == 2) ? 5 : 8;
    const int ntc = (nslot == 1 || nslot == 3) ? 2 : 3;
    // conversion roles
    const int cb = tid >> 3;            // row 0..63
    const int ksl = tid & 7;
    const int miC = cb >> 4, gC = cb & 7, halfC = (cb >> 3) & 1;
    // phase B roles
    const int zB = tid >> 8;
    const int bl = (tid >> 5) & 7;
    const int hl = tid & 31;
    const int Bbg = bid >> 4, Bhg = bid & 15;
    const int Bb = Bbg * 8 + bl, Bh = Bhg * 32 + hl;

    for (int t = 0; t < T_DIM; t++) {
        // ================= PHASE A: split-bf16 mma.sync GEMM =================
        float d[3][4];
        #pragma unroll
        for (int tt = 0; tt < 3; tt++)
            #pragma unroll
            for (int r = 0; r < 4; r++) d[tt][r] = 0.0f;

        const char* afh = smc + UN_B + mi * AF_MI + lane * 4;

        // 4 h-chunks of K=128
        for (int ch = 0; ch < 4; ch++) {
            __syncthreads();
            {
                const float* hp = g_h + cb * H_DIM + ch * 128 + ksl * 16;
                const float4 v0 = __ldcg((const float4*)hp);
                const float4 v1 = __ldcg((const float4*)(hp + 4));
                const float4 v2 = __ldcg((const float4*)(hp + 8));
                const float4 v3 = __ldcg((const float4*)(hp + 12));
                uint32_t hi[8], lo[8];
                cvt_pair(v0.x, v0.y, hi[0], lo[0]); cvt_pair(v0.z, v0.w, hi[1], lo[1]);
                cvt_pair(v1.x, v1.y, hi[2], lo[2]); cvt_pair(v1.z, v1.w, hi[3], lo[3]);
                cvt_pair(v2.x, v2.y, hi[4], lo[4]); cvt_pair(v2.z, v2.w, hi[5], lo[5]);
                cvt_pair(v3.x, v3.y, hi[6], lo[6]); cvt_pair(v3.z, v3.w, hi[7], lo[7]);
                char* b0 = smc + UN_B + miC * AF_MI + ksl * AF_KS + gC * 16;
                *(uint4*)(b0 + halfC * AF_REG)                 = make_uint4(hi[0], hi[1], hi[2], hi[3]);
                *(uint4*)(b0 + (halfC + 2) * AF_REG)           = make_uint4(hi[4], hi[5], hi[6], hi[7]);
                *(uint4*)(b0 + AF_PREC + halfC * AF_REG)       = make_uint4(lo[0], lo[1], lo[2], lo[3]);
                *(uint4*)(b0 + AF_PREC + (halfC + 2) * AF_REG) = make_uint4(lo[4], lo[5], lo[6], lo[7]);
            }
            __syncthreads();

            #pragma unroll 2
            for (int k2 = 0; k2 < 8; k2++) {
                uint32_t ah[4], al[4];
                #pragma unroll
                for (int r = 0; r < 4; r++) {
                    ah[r] = *(const uint32_t*)(afh + k2 * AF_KS + r * AF_REG);
                    al[r] = *(const uint32_t*)(afh + AF_PREC + k2 * AF_KS + r * AF_REG);
                }
                const int gks = ch * 8 + k2;
                #pragma unroll
                for (int tt = 0; tt < 3; tt++) {
                    if (tt >= ntc) break;
                    const char* bp = smc + BF_B + (nt0 + tt) * 8192 + gks * 256 + lane * 8;
                    const uint2 bh = *(const uint2*)bp;
                    const uint2 blo = *(const uint2*)(bp + 81920);
                    mma16816(d[tt], ah, bh.x, bh.y);
                    mma16816(d[tt], al, bh.x, bh.y);
                    mma16816(d[tt], ah, blo.x, blo.y);
                }
            }
        }

        // ext chunk (K=64: input projections)
        __syncthreads();
        {
            const int eks = ksl >> 1, ekh = ksl & 1;
            const int q0 = eks * 16 + ekh * 8;
            float vv[8];
            #pragma unroll
            for (int i = 0; i < 8; i++) {
                const int q = q0 + i;
                float v;
                if (q < 32) v = p.Y[((size_t)cb * 32 + q) * T_DIM + t];
                else if (q < 56) {
                    const int r2 = q - 32, xk = r2 / 3, i2 = r2 - 3 * xk;
                    v = p.x[xk][((size_t)cb * 3 + i2) * T_DIM + t];
                } else v = 0.0f;
                vv[i] = v;
            }
            uint32_t hi[4], lo[4];
            cvt_pair(vv[0], vv[1], hi[0], lo[0]); cvt_pair(vv[2], vv[3], hi[1], lo[1]);
            cvt_pair(vv[4], vv[5], hi[2], lo[2]); cvt_pair(vv[6], vv[7], hi[3], lo[3]);
            char* b0 = smc + UN_B + miC * AF_MI + eks * AF_KS + gC * 16 + (halfC + 2 * ekh) * AF_REG;
            *(uint4*)b0             = make_uint4(hi[0], hi[1], hi[2], hi[3]);
            *(uint4*)(b0 + AF_PREC) = make_uint4(lo[0], lo[1], lo[2], lo[3]);
        }
        __syncthreads();

        #pragma unroll
        for (int k2 = 0; k2 < 4; k2++) {
            uint32_t ah[4], al[4];
            #pragma unroll
            for (int r = 0; r < 4; r++) {
                ah[r] = *(const uint32_t*)(afh + k2 * AF_KS + r * AF_REG);
                al[r] = *(const uint32_t*)(afh + AF_PREC + k2 * AF_KS + r * AF_REG);
            }
            #pragma unroll
            for (int tt = 0; tt < 3; tt++) {
                if (tt >= ntc) break;
                const char* bp = smc + BEXT_B + (nt0 + tt) * 1024 + k2 * 256 + lane * 8;
                const uint2 bh = *(const uint2*)bp;
                const uint2 blo = *(const uint2*)(bp + 10240);
                mma16816(d[tt], ah, bh.x, bh.y);
                mma16816(d[tt], al, bh.x, bh.y);
                mma16816(d[tt], ah, blo.x, blo.y);
            }
        }

        // epilogue: bias + activation, write g_act (D frag: row=g(+8), colpair=c4*2)
        {
            const int g = lane >> 2, c4 = lane & 3;
            #pragma unroll
            for (int tt = 0; tt < 3; tt++) {
                if (tt >= ntc) break;
                const int cl = (nt0 + tt) * 8 + c4 * 2;
                const int gc = bid * NCOL + cl;
                const int m = gc >> 9, cc = gc & 511;
                const float b0v = bias_sm[cl], b1v = bias_sm[cl + 1];
                const float z0 = d[tt][0] + b0v, z1 = d[tt][1] + b1v;
                const float z2 = d[tt][2] + b0v, z3 = d[tt][3] + b1v;
                float r0, r1, r2, r3;
                if (m == 2 || m >= 12) {
                    r0 = tanhf(z0); r1 = tanhf(z1); r2 = tanhf(z2); r3 = tanhf(z3);
                } else {
                    r0 = sigf(z0); r1 = sigf(z1); r2 = sigf(z2); r3 = sigf(z3);
                }
                float* o0 = g_act + (size_t)m * P_SZ + (size_t)(mi * 16 + g) * H_DIM + cc;
                *(float2*)o0 = make_float2(r0, r1);
                *(float2*)(o0 + 8 * H_DIM) = make_float2(r2, r3);
            }
        }
        grid_barrier();

        // ================= PHASE B: W_a GEMM + softmax + update (SIMT) =================
        {
            float* shl = un;           // [8 b][9 k][64 j]
            float* shw = un + 4608;    // [32 h][68]
            float* shred = un + 6784;  // [256][9]

            float u9[9];
            #pragma unroll
            for (int k = 0; k < 9; k++) u9[k] = 0.0f;

            for (int ch = 0; ch < 8; ch++) {
                __syncthreads();
                for (int e = tid; e < 4608; e += BLK) {
                    const int b2 = e / 576;
                    const int r = e - b2 * 576;
                    const int k = r >> 6, j = r & 63;
                    const int gj = ch * 64 + j;
                    const float* ga = g_act + (size_t)(Bbg * 8 + b2) * H_DIM + gj;
                    float v;
                    if (k == 0) v = __ldcg(ga) * __ldcg(ga + 2 * (size_t)P_SZ);
                    else        v = __ldcg(ga + (size_t)(3 + k) * P_SZ) * __ldcg(ga + (size_t)(11 + k) * P_SZ);
                    shl[e] = v;
                }
                for (int e = tid; e < 2048; e += BLK) {
                    const int h2 = e & 31, j = e >> 5;
                    shw[h2 * 68 + j] = p.W_a[((size_t)ch * 64 + j) * H_DIM + Bhg * 32 + h2];
                }
                __syncthreads();
                const float4* lr = (const float4*)(shl + bl * 576 + zB * 32);
                const float4* wr = (const float4*)(shw + hl * 68 + zB * 32);
                #pragma unroll
                for (int j4 = 0; j4 < 8; j4++) {
                    const float4 w4 = wr[j4];
                    #pragma unroll
                    for (int k = 0; k < 9; k++) {
                        const float4 l4 = lr[k * 16 + j4];
                        u9[k] += l4.x * w4.x + l4.y * w4.y + l4.z * w4.z + l4.w * w4.w;
                    }
                }
            }

            __syncthreads();
            if (zB == 1) {
                #pragma unroll
                for (int k = 0; k < 9; k++) shred[(tid - 256) * 9 + k] = u9[k];
            }
            __syncthreads();
            if (zB == 0) {
                #pragma unroll
                for (int k = 0; k < 9; k++) u9[k] += shred[tid * 9 + k];

                const float c_old = g_c[Bb * H_DIM + Bh];
                const float ba = p.b_a[Bh];
                const float* ga = g_act + (size_t)Bb * H_DIM + Bh;

                float lv[9];
                lv[0] = __ldcg(ga) * __ldcg(ga + 2 * (size_t)P_SZ);
                #pragma unroll
                for (int k = 1; k < 9; k++)
                    lv[k] = __ldcg(ga + (size_t)(3 + k) * P_SZ) * __ldcg(ga + (size_t)(11 + k) * P_SZ);

                float uu[9], mx = -1e30f;
                #pragma unroll
                for (int k = 0; k < 9; k++) {
                    uu[k] = tanhf(u9[k] * c_old + ba);
                    mx = fmaxf(mx, uu[k]);
                }
                float se = 0.0f, L = 0.0f;
                #pragma unroll
                for (int k = 0; k < 9; k++) {
                    const float e = expf(uu[k] - mx);
                    se += e;
                    L += e * lv[k];
                }
                L /= se;

                const float cn = __ldcg(ga + 1 * (size_t)P_SZ) * c_old + L;
                const float hn = __ldcg(ga + 3 * (size_t)P_SZ) * tanhf(cn);
                g_c[Bb * H_DIM + Bh] = cn;
                g_h[Bb * H_DIM + Bh] = hn;
                out[(size_t)seq_off + ((size_t)Bb * T_DIM + t) * H_DIM + Bh] = hn;
                if (write_hT && t == T_DIM - 1)
                    out[(size_t)Bb * H_DIM + Bh] = hn;
            }
        }
        grid_barrier();
    }
}

// ---------------------------------------------------------------------
extern "C" void kernel_launch(void* const* d_in, const int* in_sizes, int n_in,
                              void* d_out, int out_size)
{
    Params p;
    p.Y = (const float*)d_in[0];
    for (int j = 0; j < 8; j++) p.x[j] = (const float*)d_in[1 + j];
    const float* W_i = (const float*)d_in[9],  *U_i = (const float*)d_in[10], *b_i = (const float*)d_in[11];
    const float* W_f = (const float*)d_in[12], *U_f = (const float*)d_in[13], *b_f = (const float*)d_in[14];
    const float* W_c = (const float*)d_in[15], *U_c = (const float*)d_in[16], *b_c = (const float*)d_in[17];
    const float* W_o = (const float*)d_in[18], *U_o = (const float*)d_in[19], *b_o = (const float*)d_in[20];
    const float* W_i_x = (const float*)d_in[21], *U_i_x = (const float*)d_in[22], *b_i_x = (const float*)d_in[23];
    const float* W_c_x = (const float*)d_in[24], *U_c_x = (const float*)d_in[25], *b_c_x = (const float*)d_in[26];
    p.W_a = (const float*)d_in[27];
    p.b_a = (const float*)d_in[28];

    // order: 0=i(sig) 1=f(sig) 2=c(tanh) 3=o(sig) 4..11=i_x(sig) 12..19=c_x(tanh)
    p.U[0] = U_i; p.U[1] = U_f; p.U[2] = U_c; p.U[3] = U_o;
    p.W[0] = W_i; p.W[1] = W_f; p.W[2] = W_c; p.W[3] = W_o;
    p.bb[0] = b_i; p.bb[1] = b_f; p.bb[2] = b_c; p.bb[3] = b_o;
    for (int k = 0; k < 8; k++) {
        p.U[4 + k]  = U_i_x + (size_t)k * H_DIM * H_DIM;
        p.U[12 + k] = U_c_x + (size_t)k * H_DIM * H_DIM;
        p.W[4 + k]  = W_i_x + (size_t)k * 3 * H_DIM;
        p.W[12 + k] = W_c_x + (size_t)k * 3 * H_DIM;
        p.bb[4 + k]  = b_i_x + (size_t)k * H_DIM;
        p.bb[12 + k] = b_c_x + (size_t)k * H_DIM;
    }

    float* out = (float*)d_out;
    const int full = B_DIM * H_DIM + B_DIM * T_DIM * H_DIM;
    const int seq_off = (out_size >= full) ? (B_DIM * H_DIM) : 0;
    const int write_hT = (seq_off != 0) ? 1 : 0;

    static int configured = 0;
    if (!configured) {
        cudaFuncSetAttribute(lstm_mma, cudaFuncAttributeMaxDynamicSharedMemorySize, SMEM_BYTES);
        configured = 1;
    }
    lstm_mma<<<GRID, BLK, SMEM_BYTES>>>(p, out, seq_off, write_hT);
}

// round 8
// speedup vs baseline: 5.3505x; 1.1061x over previous
#include <cuda_runtime.h>
#include <cuda_bf16.h>
#include <math.h>
#include <stdint.h>

#define B_DIM 64
#define T_DIM 1024
#define H_DIM 512
#define GRID  128
#define BLK   512
#define NCOL  80
#define NPAIR 40

// ---- smem byte offsets ----
#define BF_B    0        // U-pair B-frags: [nt 10][k16 32][lane 32][hi b0 b1, lo b0 b1] = 163840
#define BEXT_B  163840   // ext B-frags: [nt 10][k16 4][lane 32][16B] = 20480
#define BIAS_B  184320   // 80 floats
#define UN_B    184640   // phase A A-frags 32768 | phase B AFB 20480 + UBUF 9216
#define UBUF_B  (UN_B + 20480)
#define SMEM_BYTES (UN_B + 32768)   // 217408

// ---- device scratch ----
__device__ float g_h[B_DIM * H_DIM];
__device__ float g_c[B_DIM * H_DIM];
__device__ float g_l[B_DIM * 9 * H_DIM];
__device__ float g_f[B_DIM * H_DIM];
__device__ float g_o[B_DIM * H_DIM];
__device__ uint32_t g_wafrag[16 * 32 * 2 * 32 * 8];   // [hslice][k16][n16][lane][4hi,4lo]
__device__ unsigned g_bar_count = 0;
__device__ volatile unsigned g_bar_gen = 0;

struct Params {
    const float* U[20];
    const float* W[20];
    const float* bb[20];
    const float* Y;
    const float* x[8];
    const float* W_a;
    const float* b_a;
};

__device__ __forceinline__ float sigf(float z) { return 1.0f / (1.0f + expf(-z)); }

__device__ __forceinline__ void cvt_pair(float v0, float v1, uint32_t& hi, uint32_t& lo)
{
    const __nv_bfloat16 h0 = __float2bfloat16(v0), h1 = __float2bfloat16(v1);
    const __nv_bfloat16 l0 = __float2bfloat16(v0 - __bfloat162float(h0));
    const __nv_bfloat16 l1 = __float2bfloat16(v1 - __bfloat162float(h1));
    hi = ((uint32_t)__bfloat16_as_ushort(h1) << 16) | __bfloat16_as_ushort(h0);
    lo = ((uint32_t)__bfloat16_as_ushort(l1) << 16) | __bfloat16_as_ushort(l0);
}

__device__ __forceinline__ void mma16816(float* d, const uint32_t* a, uint32_t b0, uint32_t b1)
{
    asm volatile(
        "mma.sync.aligned.m16n8k16.row.col.f32.bf16.bf16.f32 "
        "{%0,%1,%2,%3}, {%4,%5,%6,%7}, {%8,%9}, {%0,%1,%2,%3};"
        : "+f"(d[0]), "+f"(d[1]), "+f"(d[2]), "+f"(d[3])
        : "r"(a[0]), "r"(a[1]), "r"(a[2]), "r"(a[3]), "r"(b0), "r"(b1));
}

__device__ __forceinline__ void grid_barrier()
{
    __syncthreads();
    if (threadIdx.x == 0) {
        __threadfence();
        unsigned gen = g_bar_gen;
        if (atomicAdd(&g_bar_count, 1u) == (unsigned)(gridDim.x - 1)) {
            g_bar_count = 0;
            __threadfence();
            g_bar_gen = gen + 1;
        } else {
            while (g_bar_gen == gen) { __nanosleep(32); }
            __threadfence();
        }
    }
    __syncthreads();
}

// pair type -> member matrices. ptype 0:(i,Ct) 1:(f,o) 2+k:(i_x k, c_x k)
__device__ __forceinline__ int memA(int pt) { return pt == 0 ? 0 : (pt == 1 ? 1 : pt + 2); }
__device__ __forceinline__ int memB(int pt) { return pt == 0 ? 2 : (pt == 1 ? 3 : pt + 10); }

extern __shared__ float sm[];

__global__ __launch_bounds__(BLK, 1) void lstm_mma2(Params p, float* __restrict__ out,
                                                    int seq_off, int write_hT)
{
    const int tid = threadIdx.x;
    const int bid = blockIdx.x;
    const int lane = tid & 31;
    const int wid = tid >> 5;
    char* smc = (char*)sm;
    float* bias_sm = (float*)(smc + BIAS_B);
    const uint32_t ho = lane * 32 + ((lane & 4) << 2);   // swizzled per-lane frag offset

    for (int i = bid * BLK + tid; i < B_DIM * H_DIM; i += GRID * BLK) {
        g_h[i] = 0.0f; g_c[i] = 0.0f;
    }

    // ---- one-time: U pair-columns -> B-frags ----
    for (int e = tid; e < NCOL * H_DIM; e += BLK) {
        const int s = e >> 9, j = e & 511;
        const int pq = bid * NPAIR + (s >> 1);
        const int pt = pq >> 9, c = pq & 511;
        const int m = (s & 1) ? memB(pt) : memA(pt);
        const float v = p.U[m][(size_t)j * H_DIM + c];
        const __nv_bfloat16 bh = __float2bfloat16(v);
        const __nv_bfloat16 bl = __float2bfloat16(v - __bfloat162float(bh));
        const uint32_t off = (uint32_t)(s >> 3) * 16384u + (uint32_t)(j >> 4) * 512u
                           + (uint32_t)((s & 7) * 4 + ((j & 7) >> 1)) * 16u;
        const uint32_t sl = ((j & 15) >> 3) * 4u + (j & 1) * 2u;
        *(unsigned short*)(smc + BF_B + off + sl)     = __bfloat16_as_ushort(bh);
        *(unsigned short*)(smc + BF_B + off + 8 + sl) = __bfloat16_as_ushort(bl);
    }
    for (int e = tid; e < 5120; e += BLK) ((uint32_t*)(smc + BEXT_B))[e] = 0u;
    __syncthreads();
    for (int e = tid; e < NCOL * 32; e += BLK) {
        const int s = e >> 5, i = e & 31;
        const int pq = bid * NPAIR + (s >> 1);
        const int pt = pq >> 9, c = pq & 511;
        const int m = (s & 1) ? memB(pt) : memA(pt);
        float v; int q;
        if (m < 4) { v = p.W[m][(size_t)i * H_DIM + c]; q = i; }
        else {
            if (i >= 3) continue;
            const int k = (m < 12) ? (m - 4) : (m - 12);
            const int xsel = (m < 12) ? ((k == 0) ? 0 : 1) : k;
            v = p.W[m][(size_t)i * H_DIM + c];
            q = 32 + xsel * 3 + i;
        }
        const __nv_bfloat16 bh = __float2bfloat16(v);
        const __nv_bfloat16 bl = __float2bfloat16(v - __bfloat162float(bh));
        const uint32_t off = (uint32_t)(s >> 3) * 2048u + (uint32_t)(q >> 4) * 512u
                           + (uint32_t)((s & 7) * 4 + ((q & 7) >> 1)) * 16u;
        const uint32_t sl = ((q & 15) >> 3) * 4u + (q & 1) * 2u;
        *(unsigned short*)(smc + BEXT_B + off + sl)     = __bfloat16_as_ushort(bh);
        *(unsigned short*)(smc + BEXT_B + off + 8 + sl) = __bfloat16_as_ushort(bl);
    }
    for (int s = tid; s < NCOL; s += BLK) {
        const int pq = bid * NPAIR + (s >> 1);
        const int pt = pq >> 9, c = pq & 511;
        bias_sm[s] = p.bb[(s & 1) ? memB(pt) : memA(pt)][c];
    }
    // ---- one-time: W_a -> global frag table (CTAs 0..15, slice = bid) ----
    if (bid < 16) {
        for (int e = tid; e < 16384; e += BLK) {
            const int j = e >> 5, h2 = e & 31;
            const float v = p.W_a[(size_t)j * H_DIM + bid * 32 + h2];
            const __nv_bfloat16 bh = __float2bfloat16(v);
            const __nv_bfloat16 bl = __float2bfloat16(v - __bfloat162float(bh));
            const uint32_t l2 = (h2 & 7) * 4 + ((j & 7) >> 1);
            const uint32_t sloth = ((h2 >> 3) & 1) * 2 + ((j & 15) >> 3);
            const uint32_t b32 = ((((uint32_t)bid * 32 + (j >> 4)) * 2 + (h2 >> 4)) * 32 + l2) * 8;
            ((unsigned short*)g_wafrag)[(b32 + sloth) * 2 + (j & 1)]     = __bfloat16_as_ushort(bh);
            ((unsigned short*)g_wafrag)[(b32 + 4 + sloth) * 2 + (j & 1)] = __bfloat16_as_ushort(bl);
        }
    }
    grid_barrier();

    // roles
    const int mi = wid & 3;                       // phase A m16 tile
    const int nslot = wid >> 2;
    const int nt0 = (nslot == 0) ? 0 : (nslot == 1) ? 3 : (nslot == 2) ? 5 : 8;
    const int ntc = (nslot == 1 || nslot == 3) ? 2 : 3;
    const int cb = tid >> 3, ksl = tid & 7;       // conversion
    const int miC = cb >> 4, gC = cb & 7, halfC = (cb >> 3) & 1;
    const int Bbg = bid >> 4, Bhg = bid & 15;     // phase B

    for (int t = 0; t < T_DIM; t++) {
        // ================= PHASE A =================
        float d[3][4];
        #pragma unroll
        for (int tt = 0; tt < 3; tt++) { d[tt][0]=0.f; d[tt][1]=0.f; d[tt][2]=0.f; d[tt][3]=0.f; }

        for (int ch = 0; ch < 4; ch++) {
            __syncthreads();
            {   // h -> A-frags
                const float* hp = g_h + cb * H_DIM + ch * 128 + ksl * 16;
                const float4 v0 = __ldcg((const float4*)hp);
                const float4 v1 = __ldcg((const float4*)(hp + 4));
                const float4 v2 = __ldcg((const float4*)(hp + 8));
                const float4 v3 = __ldcg((const float4*)(hp + 12));
                float vv[16] = {v0.x,v0.y,v0.z,v0.w, v1.x,v1.y,v1.z,v1.w,
                                v2.x,v2.y,v2.z,v2.w, v3.x,v3.y,v3.z,v3.w};
                char* base = smc + UN_B + (miC * 8 + ksl) * 1024;
                #pragma unroll
                for (int q = 0; q < 4; q++) {
                    uint32_t h0, l0, h1, l1;
                    cvt_pair(vv[2*q], vv[2*q+1], h0, l0);
                    cvt_pair(vv[2*q+8], vv[2*q+9], h1, l1);
                    const int l2 = gC * 4 + q;
                    const uint32_t o2 = l2 * 32 + ((l2 & 4) << 2);
                    *(uint2*)(base + o2 + halfC * 8)        = make_uint2(h0, h1);
                    *(uint2*)(base + (o2 ^ 16) + halfC * 8) = make_uint2(l0, l1);
                }
            }
            __syncthreads();
            #pragma unroll 2
            for (int k2 = 0; k2 < 8; k2++) {
                const char* ap = smc + UN_B + (mi * 8 + k2) * 1024;
                const uint4 va = *(const uint4*)(ap + ho);
                const uint4 vb = *(const uint4*)(ap + (ho ^ 16));
                const uint32_t ah[4] = {va.x, va.z, va.y, va.w};
                const uint32_t al[4] = {vb.x, vb.z, vb.y, vb.w};
                #pragma unroll
                for (int tt = 0; tt < 3; tt++) {
                    if (tt >= ntc) break;
                    const uint4 bb4 = *(const uint4*)(smc + BF_B + (nt0 + tt) * 16384
                                                      + (ch * 8 + k2) * 512 + lane * 16);
                    mma16816(d[tt], ah, bb4.x, bb4.y);
                    mma16816(d[tt], al, bb4.x, bb4.y);
                    mma16816(d[tt], ah, bb4.z, bb4.w);
                }
            }
        }
        // ext chunk (input projections)
        __syncthreads();
        {
            const int eks = ksl >> 1, ekh = ksl & 1;
            const int q0 = eks * 16 + ekh * 8;
            float vv[8];
            #pragma unroll
            for (int i = 0; i < 8; i++) {
                const int q = q0 + i;
                float v;
                if (q < 32) v = p.Y[((size_t)cb * 32 + q) * T_DIM + t];
                else if (q < 56) {
                    const int r2 = q - 32, xk = r2 / 3, i2 = r2 - 3 * xk;
                    v = p.x[xk][((size_t)cb * 3 + i2) * T_DIM + t];
                } else v = 0.0f;
                vv[i] = v;
            }
            char* base = smc + UN_B + (miC * 8 + eks) * 1024;
            const int slot = halfC * 2 + ekh;
            #pragma unroll
            for (int q = 0; q < 4; q++) {
                uint32_t h0, l0;
                cvt_pair(vv[2*q], vv[2*q+1], h0, l0);
                const int l2 = gC * 4 + q;
                const uint32_t o2 = l2 * 32 + ((l2 & 4) << 2);
                *(uint32_t*)(base + o2 + slot * 4)        = h0;
                *(uint32_t*)(base + (o2 ^ 16) + slot * 4) = l0;
            }
        }
        __syncthreads();
        #pragma unroll
        for (int k2 = 0; k2 < 4; k2++) {
            const char* ap = smc + UN_B + (mi * 8 + k2) * 1024;
            const uint4 va = *(const uint4*)(ap + ho);
            const uint4 vb = *(const uint4*)(ap + (ho ^ 16));
            const uint32_t ah[4] = {va.x, va.z, va.y, va.w};
            const uint32_t al[4] = {vb.x, vb.z, vb.y, vb.w};
            #pragma unroll
            for (int tt = 0; tt < 3; tt++) {
                if (tt >= ntc) break;
                const uint4 bb4 = *(const uint4*)(smc + BEXT_B + (nt0 + tt) * 2048
                                                  + k2 * 512 + lane * 16);
                mma16816(d[tt], ah, bb4.x, bb4.y);
                mma16816(d[tt], al, bb4.x, bb4.y);
                mma16816(d[tt], ah, bb4.z, bb4.w);
            }
        }
        // epilogue: pairs -> l / f,o
        {
            const int g = lane >> 2, c4 = lane & 3;
            #pragma unroll
            for (int tt = 0; tt < 3; tt++) {
                if (tt >= ntc) break;
                const int cl = (nt0 + tt) * 8 + c4 * 2;
                const int pq = bid * NPAIR + (cl >> 1);
                const int pt = pq >> 9, c = pq & 511;
                const float bA = bias_sm[cl], bB = bias_sm[cl + 1];
                const int b0 = mi * 16 + g, b1 = b0 + 8;
                const float sA0 = sigf(d[tt][0] + bA), sA1 = sigf(d[tt][2] + bA);
                if (pt == 1) {
                    g_f[b0 * H_DIM + c] = sA0;
                    g_f[b1 * H_DIM + c] = sA1;
                    g_o[b0 * H_DIM + c] = sigf(d[tt][1] + bB);
                    g_o[b1 * H_DIM + c] = sigf(d[tt][3] + bB);
                } else {
                    const int kk = (pt == 0) ? 0 : pt - 1;
                    g_l[((size_t)b0 * 9 + kk) * H_DIM + c] = sA0 * tanhf(d[tt][1] + bB);
                    g_l[((size_t)b1 * 9 + kk) * H_DIM + c] = sA1 * tanhf(d[tt][3] + bB);
                }
            }
        }
        grid_barrier();

        // ================= PHASE B: u = l @ W_a via mma =================
        float d2[2][4];
        #pragma unroll
        for (int n8 = 0; n8 < 2; n8++) { d2[n8][0]=0.f; d2[n8][1]=0.f; d2[n8][2]=0.f; d2[n8][3]=0.f; }

        for (int ch = 0; ch < 8; ch++) {
            __syncthreads();
            if (ch == 0) {
                // zero pad rows 72..79 (mi=4, rowhalf=1 slots)
                if (tid < 128) {
                    const int kl = tid >> 5, l2 = tid & 31;
                    char* base = smc + UN_B + (16 + kl) * 1024;
                    const uint32_t o2 = l2 * 32 + ((l2 & 4) << 2);
                    *(uint2*)(base + o2 + 8) = make_uint2(0u, 0u);
                    *(uint2*)(base + (o2 ^ 16) + 8) = make_uint2(0u, 0u);
                }
            }
            for (int e = tid; e < 2304; e += BLK) {
                const int r = e >> 5, jp = e & 31, j = jp * 2;
                const int b = r & 7, k = r >> 3;
                const float2 lv2 = __ldcg((const float2*)(
                    g_l + ((size_t)(Bbg * 8 + b) * 9 + k) * H_DIM + ch * 64 + j));
                uint32_t hi, lo;
                cvt_pair(lv2.x, lv2.y, hi, lo);
                const int mi2 = r >> 4, rowhalf = (r >> 3) & 1;
                const int l2 = (r & 7) * 4 + ((j & 7) >> 1);
                const int slot = rowhalf * 2 + ((j >> 3) & 1);
                char* base = smc + UN_B + (mi2 * 4 + (j >> 4)) * 1024;
                const uint32_t o2 = l2 * 32 + ((l2 & 4) << 2);
                *(uint32_t*)(base + o2 + slot * 4)        = hi;
                *(uint32_t*)(base + (o2 ^ 16) + slot * 4) = lo;
            }
            __syncthreads();
            if (wid < 10) {
                const int mi2 = wid >> 1, n16 = wid & 1;
                #pragma unroll
                for (int kl = 0; kl < 4; kl++) {
                    const char* ap = smc + UN_B + (mi2 * 4 + kl) * 1024;
                    const uint4 va = *(const uint4*)(ap + ho);
                    const uint4 vb = *(const uint4*)(ap + (ho ^ 16));
                    const uint32_t ah[4] = {va.x, va.z, va.y, va.w};
                    const uint32_t al[4] = {vb.x, vb.z, vb.y, vb.w};
                    const uint32_t idx = ((((uint32_t)Bhg * 32 + ch * 4 + kl) * 2 + n16) * 32 + lane) * 8;
                    const uint4 wh = __ldg((const uint4*)(g_wafrag + idx));
                    const uint4 wl = __ldg((const uint4*)(g_wafrag + idx) + 1);
                    mma16816(d2[0], ah, wh.x, wh.y);
                    mma16816(d2[0], al, wh.x, wh.y);
                    mma16816(d2[0], ah, wl.x, wl.y);
                    mma16816(d2[1], ah, wh.z, wh.w);
                    mma16816(d2[1], al, wh.z, wh.w);
                    mma16816(d2[1], ah, wl.z, wl.w);
                }
            }
        }
        // write u to smem u_buf
        if (wid < 10) {
            const int mi2 = wid >> 1, n16 = wid & 1;
            float* ub = (float*)(smc + UBUF_B);
            const int r0 = mi2 * 16 + (lane >> 2), r1 = r0 + 8;
            #pragma unroll
            for (int n8 = 0; n8 < 2; n8++) {
                const int n0 = n16 * 16 + n8 * 8 + (lane & 3) * 2;
                ub[r0 * 32 + n0]     = d2[n8][0];
                ub[r0 * 32 + n0 + 1] = d2[n8][1];
                if (r1 < 72) {
                    ub[r1 * 32 + n0]     = d2[n8][2];
                    ub[r1 * 32 + n0 + 1] = d2[n8][3];
                }
            }
        }
        __syncthreads();
        // final combine
        if (tid < 256) {
            const int bl2 = tid >> 5, hl2 = tid & 31;
            const int b = Bbg * 8 + bl2, h = Bhg * 32 + hl2;
            const float* ub = (const float*)(smc + UBUF_B);
            const float c_old = g_c[b * H_DIM + h];
            const float ba = p.b_a[h];
            float uu[9], mx = -1e30f;
            #pragma unroll
            for (int k = 0; k < 9; k++) {
                const float u = ub[(k * 8 + bl2) * 32 + hl2];
                uu[k] = tanhf(u * c_old + ba);
                mx = fmaxf(mx, uu[k]);
            }
            float se = 0.0f, L = 0.0f;
            #pragma unroll
            for (int k = 0; k < 9; k++) {
                const float e = expf(uu[k] - mx);
                se += e;
                L += e * __ldcg(g_l + ((size_t)b * 9 + k) * H_DIM + h);
            }
            L /= se;
            const float cn = __ldcg(g_f + b * H_DIM + h) * c_old + L;
            const float hn = __ldcg(g_o + b * H_DIM + h) * tanhf(cn);
            g_c[b * H_DIM + h] = cn;
            g_h[b * H_DIM + h] = hn;
            out[(size_t)seq_off + ((size_t)b * T_DIM + t) * H_DIM + h] = hn;
            if (write_hT && t == T_DIM - 1)
                out[(size_t)b * H_DIM + h] = hn;
        }
        grid_barrier();
    }
}

// ---------------------------------------------------------------------
extern "C" void kernel_launch(void* const* d_in, const int* in_sizes, int n_in,
                              void* d_out, int out_size)
{
    Params p;
    p.Y = (const float*)d_in[0];
    for (int j = 0; j < 8; j++) p.x[j] = (const float*)d_in[1 + j];
    const float* W_i = (const float*)d_in[9],  *U_i = (const float*)d_in[10], *b_i = (const float*)d_in[11];
    const float* W_f = (const float*)d_in[12], *U_f = (const float*)d_in[13], *b_f = (const float*)d_in[14];
    const float* W_c = (const float*)d_in[15], *U_c = (const float*)d_in[16], *b_c = (const float*)d_in[17];
    const float* W_o = (const float*)d_in[18], *U_o = (const float*)d_in[19], *b_o = (const float*)d_in[20];
    const float* W_i_x = (const float*)d_in[21], *U_i_x = (const float*)d_in[22], *b_i_x = (const float*)d_in[23];
    const float* W_c_x = (const float*)d_in[24], *U_c_x = (const float*)d_in[25], *b_c_x = (const float*)d_in[26];
    p.W_a = (const float*)d_in[27];
    p.b_a = (const float*)d_in[28];

    p.U[0] = U_i; p.U[1] = U_f; p.U[2] = U_c; p.U[3] = U_o;
    p.W[0] = W_i; p.W[1] = W_f; p.W[2] = W_c; p.W[3] = W_o;
    p.bb[0] = b_i; p.bb[1] = b_f; p.bb[2] = b_c; p.bb[3] = b_o;
    for (int k = 0; k < 8; k++) {
        p.U[4 + k]  = U_i_x + (size_t)k * H_DIM * H_DIM;
        p.U[12 + k] = U_c_x + (size_t)k * H_DIM * H_DIM;
        p.W[4 + k]  = W_i_x + (size_t)k * 3 * H_DIM;
        p.W[12 + k] = W_c_x + (size_t)k * 3 * H_DIM;
        p.bb[4 + k]  = b_i_x + (size_t)k * H_DIM;
        p.bb[12 + k] = b_c_x + (size_t)k * H_DIM;
    }

    float* out = (float*)d_out;
    const int full = B_DIM * H_DIM + B_DIM * T_DIM * H_DIM;
    const int seq_off = (out_size >= full) ? (B_DIM * H_DIM) : 0;
    const int write_hT = (seq_off != 0) ? 1 : 0;

    static int configured = 0;
    if (!configured) {
        cudaFuncSetAttribute(lstm_mma2, cudaFuncAttributeMaxDynamicSharedMemorySize, SMEM_BYTES);
        configured = 1;
    }
    lstm_mma2<<<GRID, BLK, SMEM_BYTES>>>(p, out, seq_off, write_hT);
}

// round 9
// speedup vs baseline: 10.5335x; 1.9687x over previous
#include <cuda_runtime.h>
#include <cuda_bf16.h>
#include <math.h>
#include <stdint.h>

#define B_DIM 64
#define T_DIM 1024
#define H_DIM 512
#define GRID  128
#define BLK   512
#define NPAIR 40

// ---- smem byte offsets ----
#define BF_B    0        // U-pair B-frags: [nt 10][k16 32][lane 32][16B: hi2,lo2]
#define BEXT_B  163840   // ext B-frags: [nt 10][k16 4][lane 32][16B]
#define BIAS_B  184320   // 80 floats
#define UBUF_B  184640   // u buffer 72x32 fp32 = 9216B
#define SMEM_BYTES 193856

// ---- device scratch ----
__device__ uint32_t g_hp[32 * 4 * 32 * 8];            // h A-frags [k16][mi][lane][4hi,4lo]
__device__ uint32_t g_lp[8 * 32 * 5 * 32 * 8];        // l A-frags [Bbg][j16][mi2][lane][8]
__device__ uint32_t g_ep[1024u * 4 * 4 * 32 * 8];     // ext A-frags [t][ek][mi][lane][8]
__device__ uint32_t g_wafrag[16 * 32 * 2 * 32 * 8];   // W_a B-frags [Bhg][k16][n16][lane][8]
__device__ float g_c[B_DIM * H_DIM];
__device__ float g_l[B_DIM * 9 * H_DIM];
__device__ float g_f[B_DIM * H_DIM];
__device__ float g_o[B_DIM * H_DIM];
__device__ unsigned g_bar_count = 0;
__device__ volatile unsigned g_bar_gen = 0;

struct Params {
    const float* U[20];
    const float* W[20];
    const float* bb[20];
    const float* Y;
    const float* x[8];
    const float* W_a;
    const float* b_a;
};

__device__ __forceinline__ float sigf(float z) { return 1.0f / (1.0f + expf(-z)); }

__device__ __forceinline__ void cvt_pair(float v0, float v1, uint32_t& hi, uint32_t& lo)
{
    const __nv_bfloat16 h0 = __float2bfloat16(v0), h1 = __float2bfloat16(v1);
    const __nv_bfloat16 l0 = __float2bfloat16(v0 - __bfloat162float(h0));
    const __nv_bfloat16 l1 = __float2bfloat16(v1 - __bfloat162float(h1));
    hi = ((uint32_t)__bfloat16_as_ushort(h1) << 16) | __bfloat16_as_ushort(h0);
    lo = ((uint32_t)__bfloat16_as_ushort(l1) << 16) | __bfloat16_as_ushort(l0);
}

__device__ __forceinline__ void mma16816(float* d, const uint32_t* a, uint32_t b0, uint32_t b1)
{
    asm volatile(
        "mma.sync.aligned.m16n8k16.row.col.f32.bf16.bf16.f32 "
        "{%0,%1,%2,%3}, {%4,%5,%6,%7}, {%8,%9}, {%0,%1,%2,%3};"
        : "+f"(d[0]), "+f"(d[1]), "+f"(d[2]), "+f"(d[3])
        : "r"(a[0]), "r"(a[1]), "r"(a[2]), "r"(a[3]), "r"(b0), "r"(b1));
}

// grid barrier with gpu-scope fences on BOTH sides of the release so every
// CTA's L1 is invalidated after all peers' writes (CCTL.IVALL via fence.gpu)
__device__ __forceinline__ void grid_barrier()
{
    __syncthreads();
    if (threadIdx.x == 0) {
        __threadfence();
        unsigned gen = g_bar_gen;
        if (atomicAdd(&g_bar_count, 1u) == (unsigned)(gridDim.x - 1)) {
            g_bar_count = 0;
            __threadfence();
            g_bar_gen = gen + 1;
            __threadfence();
        } else {
            while (g_bar_gen == gen) { __nanosleep(32); }
            __threadfence();
        }
    }
    __syncthreads();
}

// pair type -> member matrices. pt 0:(i,Ct) 1:(f,o) 2+k:(i_x k, c_x k)
__device__ __forceinline__ int memA(int pt) { return pt == 0 ? 0 : (pt == 1 ? 1 : pt + 2); }
__device__ __forceinline__ int memB(int pt) { return pt == 0 ? 2 : (pt == 1 ? 3 : pt + 10); }

extern __shared__ float sm[];

__global__ __launch_bounds__(BLK, 1) void lstm_frag(Params p, float* __restrict__ out,
                                                    int seq_off, int write_hT)
{
    const int tid = threadIdx.x;
    const int bid = blockIdx.x;
    const int lane = tid & 31;
    const int wid = tid >> 5;
    const int gtid = bid * BLK + tid;
    char* smc = (char*)sm;
    float* bias_sm = (float*)(smc + BIAS_B);
    float* ub = (float*)(smc + UBUF_B);

    // ---- zero dynamic frag tables + c ----
    for (int i = gtid; i < 32 * 4 * 32 * 8; i += GRID * BLK) g_hp[i] = 0u;
    for (int i = gtid; i < 8 * 32 * 5 * 32 * 8; i += GRID * BLK) g_lp[i] = 0u;
    for (int i = gtid; i < B_DIM * H_DIM; i += GRID * BLK) g_c[i] = 0.0f;

    // ---- one-time: ext input A-frags for ALL t ----
    for (int idx = gtid; idx < T_DIM * 2048; idx += GRID * BLK) {
        const int t = idx >> 11;
        const int r = idx & 2047;
        const int b = r >> 5, qp = r & 31, q = qp * 2;
        float v0, v1;
        {
            const int qq = q;
            if (qq < 32) v0 = p.Y[((size_t)b * 32 + qq) * T_DIM + t];
            else if (qq < 56) { const int rr = qq - 32, xk = rr / 3, i2 = rr - 3 * xk;
                                v0 = p.x[xk][((size_t)b * 3 + i2) * T_DIM + t]; }
            else v0 = 0.0f;
        }
        {
            const int qq = q + 1;
            if (qq < 32) v1 = p.Y[((size_t)b * 32 + qq) * T_DIM + t];
            else if (qq < 56) { const int rr = qq - 32, xk = rr / 3, i2 = rr - 3 * xk;
                                v1 = p.x[xk][((size_t)b * 3 + i2) * T_DIM + t]; }
            else v1 = 0.0f;
        }
        uint32_t hi, lo; cvt_pair(v0, v1, hi, lo);
        const int lane2 = (b & 7) * 4 + ((q & 7) >> 1);
        const int slot = ((b >> 3) & 1) * 2 + ((q & 15) >> 3);
        const size_t base = ((((size_t)t * 4 + (q >> 4)) * 4 + (b >> 4)) * 32 + lane2) * 8 + slot;
        g_ep[base] = hi; g_ep[base + 4] = lo;
    }

    // ---- one-time: U pair-columns -> B-frags (smem) ----
    for (int e = tid; e < 80 * H_DIM; e += BLK) {
        const int s = e >> 9, j = e & 511;
        const int pq = bid * NPAIR + (s >> 1);
        const int pt = pq >> 9, c = pq & 511;
        const int m = (s & 1) ? memB(pt) : memA(pt);
        const float v = p.U[m][(size_t)j * H_DIM + c];
        const __nv_bfloat16 bh = __float2bfloat16(v);
        const __nv_bfloat16 bl = __float2bfloat16(v - __bfloat162float(bh));
        const uint32_t off = (uint32_t)(s >> 3) * 16384u + (uint32_t)(j >> 4) * 512u
                           + (uint32_t)((s & 7) * 4 + ((j & 7) >> 1)) * 16u;
        const uint32_t sl = ((j & 15) >> 3) * 4u + (j & 1) * 2u;
        *(unsigned short*)(smc + BF_B + off + sl)     = __bfloat16_as_ushort(bh);
        *(unsigned short*)(smc + BF_B + off + 8 + sl) = __bfloat16_as_ushort(bl);
    }
    for (int e = tid; e < 5120; e += BLK) ((uint32_t*)(smc + BEXT_B))[e] = 0u;
    __syncthreads();
    for (int e = tid; e < 80 * 32; e += BLK) {
        const int s = e >> 5, i = e & 31;
        const int pq = bid * NPAIR + (s >> 1);
        const int pt = pq >> 9, c = pq & 511;
        const int m = (s & 1) ? memB(pt) : memA(pt);
        float v; int q;
        if (m < 4) { v = p.W[m][(size_t)i * H_DIM + c]; q = i; }
        else {
            if (i >= 3) continue;
            const int k = (m < 12) ? (m - 4) : (m - 12);
            const int xsel = (m < 12) ? ((k == 0) ? 0 : 1) : k;
            v = p.W[m][(size_t)i * H_DIM + c];
            q = 32 + xsel * 3 + i;
        }
        const __nv_bfloat16 bh = __float2bfloat16(v);
        const __nv_bfloat16 bl = __float2bfloat16(v - __bfloat162float(bh));
        const uint32_t off = (uint32_t)(s >> 3) * 2048u + (uint32_t)(q >> 4) * 512u
                           + (uint32_t)((s & 7) * 4 + ((q & 7) >> 1)) * 16u;
        const uint32_t sl = ((q & 15) >> 3) * 4u + (q & 1) * 2u;
        *(unsigned short*)(smc + BEXT_B + off + sl)     = __bfloat16_as_ushort(bh);
        *(unsigned short*)(smc + BEXT_B + off + 8 + sl) = __bfloat16_as_ushort(bl);
    }
    for (int s = tid; s < 80; s += BLK) {
        const int pq = bid * NPAIR + (s >> 1);
        const int pt = pq >> 9, c = pq & 511;
        bias_sm[s] = p.bb[(s & 1) ? memB(pt) : memA(pt)][c];
    }
    // ---- one-time: W_a -> global B-frag table (CTAs 0..15) ----
    if (bid < 16) {
        for (int e = tid; e < 16384; e += BLK) {
            const int j = e >> 5, h2 = e & 31;
            const float v = p.W_a[(size_t)j * H_DIM + bid * 32 + h2];
            const __nv_bfloat16 bh = __float2bfloat16(v);
            const __nv_bfloat16 bl = __float2bfloat16(v - __bfloat162float(bh));
            const uint32_t l2 = (h2 & 7) * 4 + ((j & 7) >> 1);
            const uint32_t sloth = ((h2 >> 3) & 1) * 2 + ((j & 15) >> 3);
            const uint32_t b32 = ((((uint32_t)bid * 32 + (j >> 4)) * 2 + (h2 >> 4)) * 32 + l2) * 8;
            ((unsigned short*)g_wafrag)[(b32 + sloth) * 2 + (j & 1)]     = __bfloat16_as_ushort(bh);
            ((unsigned short*)g_wafrag)[(b32 + 4 + sloth) * 2 + (j & 1)] = __bfloat16_as_ushort(bl);
        }
    }
    grid_barrier();

    // roles
    const int mi = wid & 3;
    const int nslot = wid >> 2;
    const int nt0 = (nslot == 0) ? 0 : (nslot == 1) ? 3 : (nslot == 2) ? 5 : 8;
    const int ntc = (nslot == 1 || nslot == 3) ? 2 : 3;
    const int g = lane >> 2, c4 = lane & 3;
    const int Bbg = bid >> 4, Bhg = bid & 15;

    for (int t = 0; t < T_DIM; t++) {
        // ================= PHASE A: pure LDG+LDS+HMMA =================
        float d[3][4];
        #pragma unroll
        for (int tt = 0; tt < 3; tt++) { d[tt][0]=0.f; d[tt][1]=0.f; d[tt][2]=0.f; d[tt][3]=0.f; }

        #pragma unroll 4
        for (int kt = 0; kt < 32; kt++) {
            const uint4* ap = (const uint4*)(g_hp + (((size_t)kt * 4 + mi) * 32 + lane) * 8);
            const uint4 hv = __ldg(ap), lv = __ldg(ap + 1);
            const uint32_t ah[4] = {hv.x, hv.z, hv.y, hv.w};
            const uint32_t al[4] = {lv.x, lv.z, lv.y, lv.w};
            #pragma unroll
            for (int tt = 0; tt < 3; tt++) {
                if (tt >= ntc) break;
                const uint4 b4 = *(const uint4*)(smc + BF_B + (nt0 + tt) * 16384 + kt * 512 + lane * 16);
                mma16816(d[tt], ah, b4.x, b4.y);
                mma16816(d[tt], al, b4.x, b4.y);
                mma16816(d[tt], ah, b4.z, b4.w);
            }
        }
        #pragma unroll
        for (int ek = 0; ek < 4; ek++) {
            const uint4* ap = (const uint4*)(g_ep + ((((size_t)t * 4 + ek) * 4 + mi) * 32 + lane) * 8);
            const uint4 hv = __ldg(ap), lv = __ldg(ap + 1);
            const uint32_t ah[4] = {hv.x, hv.z, hv.y, hv.w};
            const uint32_t al[4] = {lv.x, lv.z, lv.y, lv.w};
            #pragma unroll
            for (int tt = 0; tt < 3; tt++) {
                if (tt >= ntc) break;
                const uint4 b4 = *(const uint4*)(smc + BEXT_B + (nt0 + tt) * 2048 + ek * 512 + lane * 16);
                mma16816(d[tt], ah, b4.x, b4.y);
                mma16816(d[tt], al, b4.x, b4.y);
                mma16816(d[tt], ah, b4.z, b4.w);
            }
        }

        // epilogue: activations, fp32 l/f/o stores + packed l frag stores
        #pragma unroll
        for (int tt = 0; tt < 3; tt++) {
            if (tt >= ntc) break;
            const int cl = (nt0 + tt) * 8 + c4 * 2;
            const int pq = bid * NPAIR + (cl >> 1);
            const int pt = pq >> 9, c = pq & 511;
            const float bA = bias_sm[cl], bB = bias_sm[cl + 1];
            const int b0 = mi * 16 + g, b1 = b0 + 8;
            const float sA0 = sigf(d[tt][0] + bA), sA1 = sigf(d[tt][2] + bA);
            if (pt == 1) {
                g_f[b0 * H_DIM + c] = sA0;
                g_f[b1 * H_DIM + c] = sA1;
                g_o[b0 * H_DIM + c] = sigf(d[tt][1] + bB);
                g_o[b1 * H_DIM + c] = sigf(d[tt][3] + bB);
            } else {
                const int kk = (pt == 0) ? 0 : pt - 1;
                const float lv0 = sA0 * tanhf(d[tt][1] + bB);
                const float lv1 = sA1 * tanhf(d[tt][3] + bB);
                g_l[((size_t)b0 * 9 + kk) * H_DIM + c] = lv0;
                g_l[((size_t)b1 * 9 + kk) * H_DIM + c] = lv1;
                // packed A-frag stores (pair across adjacent c via shfl)
                const float n0 = __shfl_xor_sync(0xFFFFFFFFu, lv0, 1);
                const float n1 = __shfl_xor_sync(0xFFFFFFFFu, lv1, 1);
                const int ev = !(c4 & 1);
                const float pe0 = ev ? lv0 : n0, po0 = ev ? n0 : lv0;
                const float pe1 = ev ? lv1 : n1, po1 = ev ? n1 : lv1;
                const int cE = c & ~1;
                uint32_t hi0, lo0, hi1, lo1;
                cvt_pair(pe0, po0, hi0, lo0);
                cvt_pair(pe1, po1, hi1, lo1);
                const int lane2 = g * 4 + ((cE & 7) >> 1);
                const int slot = (kk & 1) * 2 + ((cE & 15) >> 3);
                const int mi2 = kk >> 1, j16 = cE >> 4;
                const int s = ev ? slot : (slot + 4);
                const uint32_t w0 = ev ? hi0 : lo0;
                const uint32_t w1 = ev ? hi1 : lo1;
                g_lp[((((size_t)(mi * 2) * 32 + j16) * 5 + mi2) * 32 + lane2) * 8 + s] = w0;
                g_lp[((((size_t)(mi * 2 + 1) * 32 + j16) * 5 + mi2) * 32 + lane2) * 8 + s] = w1;
            }
        }
        grid_barrier();

        // ================= PHASE B: pure LDG+HMMA =================
        if (wid < 10) {
            float d2[2][4];
            #pragma unroll
            for (int n8 = 0; n8 < 2; n8++) { d2[n8][0]=0.f; d2[n8][1]=0.f; d2[n8][2]=0.f; d2[n8][3]=0.f; }
            const int mi2w = wid >> 1, n16 = wid & 1;
            #pragma unroll 4
            for (int kl = 0; kl < 32; kl++) {
                const uint4* ap = (const uint4*)(g_lp + ((((size_t)Bbg * 32 + kl) * 5 + mi2w) * 32 + lane) * 8);
                const uint4 hv = __ldg(ap), lv = __ldg(ap + 1);
                const uint32_t ah[4] = {hv.x, hv.z, hv.y, hv.w};
                const uint32_t al[4] = {lv.x, lv.z, lv.y, lv.w};
                const uint4* wp = (const uint4*)(g_wafrag + ((((size_t)Bhg * 32 + kl) * 2 + n16) * 32 + lane) * 8);
                const uint4 wh = __ldg(wp), wl = __ldg(wp + 1);
                mma16816(d2[0], ah, wh.x, wh.y);
                mma16816(d2[0], al, wh.x, wh.y);
                mma16816(d2[0], ah, wl.x, wl.y);
                mma16816(d2[1], ah, wh.z, wh.w);
                mma16816(d2[1], al, wh.z, wh.w);
                mma16816(d2[1], ah, wl.z, wl.w);
            }
            const int r0 = mi2w * 16 + g, r1 = r0 + 8;
            #pragma unroll
            for (int n8 = 0; n8 < 2; n8++) {
                const int n0 = n16 * 16 + n8 * 8 + c4 * 2;
                ub[r0 * 32 + n0]     = d2[n8][0];
                ub[r0 * 32 + n0 + 1] = d2[n8][1];
                if (r1 < 72) {
                    ub[r1 * 32 + n0]     = d2[n8][2];
                    ub[r1 * 32 + n0 + 1] = d2[n8][3];
                }
            }
        }
        __syncthreads();

        // combine + packed h store
        if (tid < 256) {
            const int bl2 = tid >> 5, hl2 = tid & 31;
            const int b = Bbg * 8 + bl2, h = Bhg * 32 + hl2;
            const float c_old = g_c[b * H_DIM + h];
            const float ba = p.b_a[h];
            float uu[9], mx = -1e30f;
            #pragma unroll
            for (int k = 0; k < 9; k++) {
                const float u = ub[(k * 8 + bl2) * 32 + hl2];
                uu[k] = tanhf(u * c_old + ba);
                mx = fmaxf(mx, uu[k]);
            }
            float se = 0.0f, L = 0.0f;
            #pragma unroll
            for (int k = 0; k < 9; k++) {
                const float e = expf(uu[k] - mx);
                se += e;
                L += e * __ldcg(g_l + ((size_t)b * 9 + k) * H_DIM + h);
            }
            L /= se;
            const float cn = __ldcg(g_f + b * H_DIM + h) * c_old + L;
            const float hn = __ldcg(g_o + b * H_DIM + h) * tanhf(cn);
            g_c[b * H_DIM + h] = cn;

            const float nh = __shfl_xor_sync(0xFFFFFFFFu, hn, 1);
            const int ev = !(hl2 & 1);
            const float pe = ev ? hn : nh, po = ev ? nh : hn;
            uint32_t hi, lo;
            cvt_pair(pe, po, hi, lo);
            const int hE = h & ~1;
            const int lane2 = (b & 7) * 4 + ((hE & 7) >> 1);
            const int slot = ((b >> 3) & 1) * 2 + ((hE & 15) >> 3);
            const size_t dst = (((size_t)(hE >> 4) * 4 + (b >> 4)) * 32 + lane2) * 8;
            g_hp[dst + (ev ? slot : slot + 4)] = ev ? hi : lo;

            out[(size_t)seq_off + ((size_t)b * T_DIM + t) * H_DIM + h] = hn;
            if (write_hT && t == T_DIM - 1)
                out[(size_t)b * H_DIM + h] = hn;
        }
        grid_barrier();
    }
}

// ---------------------------------------------------------------------
extern "C" void kernel_launch(void* const* d_in, const int* in_sizes, int n_in,
                              void* d_out, int out_size)
{
    Params p;
    p.Y = (const float*)d_in[0];
    for (int j = 0; j < 8; j++) p.x[j] = (const float*)d_in[1 + j];
    const float* W_i = (const float*)d_in[9],  *U_i = (const float*)d_in[10], *b_i = (const float*)d_in[11];
    const float* W_f = (const float*)d_in[12], *U_f = (const float*)d_in[13], *b_f = (const float*)d_in[14];
    const float* W_c = (const float*)d_in[15], *U_c = (const float*)d_in[16], *b_c = (const float*)d_in[17];
    const float* W_o = (const float*)d_in[18], *U_o = (const float*)d_in[19], *b_o = (const float*)d_in[20];
    const float* W_i_x = (const float*)d_in[21], *U_i_x = (const float*)d_in[22], *b_i_x = (const float*)d_in[23];
    const float* W_c_x = (const float*)d_in[24], *U_c_x = (const float*)d_in[25], *b_c_x = (const float*)d_in[26];
    p.W_a = (const float*)d_in[27];
    p.b_a = (const float*)d_in[28];

    p.U[0] = U_i; p.U[1] = U_f; p.U[2] = U_c; p.U[3] = U_o;
    p.W[0] = W_i; p.W[1] = W_f; p.W[2] = W_c; p.W[3] = W_o;
    p.bb[0] = b_i; p.bb[1] = b_f; p.bb[2] = b_c; p.bb[3] = b_o;
    for (int k = 0; k < 8; k++) {
        p.U[4 + k]  = U_i_x + (size_t)k * H_DIM * H_DIM;
        p.U[12 + k] = U_c_x + (size_t)k * H_DIM * H_DIM;
        p.W[4 + k]  = W_i_x + (size_t)k * 3 * H_DIM;
        p.W[12 + k] = W_c_x + (size_t)k * 3 * H_DIM;
        p.bb[4 + k]  = b_i_x + (size_t)k * H_DIM;
        p.bb[12 + k] = b_c_x + (size_t)k * H_DIM;
    }

    float* out = (float*)d_out;
    const int full = B_DIM * H_DIM + B_DIM * T_DIM * H_DIM;
    const int seq_off = (out_size >= full) ? (B_DIM * H_DIM) : 0;
    const int write_hT = (seq_off != 0) ? 1 : 0;

    static int configured = 0;
    if (!configured) {
        cudaFuncSetAttribute(lstm_frag, cudaFuncAttributeMaxDynamicSharedMemorySize, SMEM_BYTES);
        configured = 1;
    }
    lstm_frag<<<GRID, BLK, SMEM_BYTES>>>(p, out, seq_off, write_hT);
}

// round 10
// speedup vs baseline: 10.7243x; 1.0181x over previous
#include <cuda_runtime.h>
#include <cuda_fp16.h>
#include <math.h>
#include <stdint.h>

#define B_DIM 64
#define T_DIM 1024
#define H_DIM 512
#define GRID  128
#define BLK   512
#define NPAIR 40

// ---- smem byte offsets ----
#define BF_B    0         // U-pair B-frags fp16: [nt10][kt32][lane32][8B] = 81920
#define BEXT_B  81920     // ext B-frags fp16: [nt10][ek4][lane32][8B] = 10240
#define WAS_B   92160     // W_a B-frags fp16: [kl32][n16 2][lane32][16B] = 32768
#define BIAS_B  124928    // 80 floats
#define UBUF_B  125248    // 72x32 fp32 = 9216
#define ASTG_B  134528    // A-stage double buffer 2x32KB (128B aligned)
#define SMEM_BYTES 200064

// ---- device scratch ----
__device__ uint32_t g_hp[32 * 4 * 32 * 8];          // h A-frags [kt][mi][lane][4hi,4lo] fp16
__device__ uint32_t g_lp[8 * 32 * 5 * 32 * 8];      // l A-frags [Bbg][kl][mi2][lane][8] fp16
__device__ uint32_t g_ep[1024u * 4 * 4 * 32 * 8];   // ext A-frags [t][ek][mi][lane][8] fp16
__device__ float g_c[B_DIM * H_DIM];
__device__ float g_l[B_DIM * 9 * H_DIM];
__device__ float g_f[B_DIM * H_DIM];
__device__ float g_o[B_DIM * H_DIM];
__device__ unsigned g_bar_count = 0;
__device__ volatile unsigned g_bar_gen = 0;

struct Params {
    const float* U[20];
    const float* W[20];
    const float* bb[20];
    const float* Y;
    const float* x[8];
    const float* W_a;
    const float* b_a;
};

__device__ __forceinline__ float sigf(float z) { return 1.0f / (1.0f + expf(-z)); }

// split-fp16 pair: hi word packs rn(v0),rn(v1); lo packs the residuals
__device__ __forceinline__ void cvt_pair_h(float v0, float v1, uint32_t& hi, uint32_t& lo)
{
    const __half h0 = __float2half_rn(v0), h1 = __float2half_rn(v1);
    const __half l0 = __float2half_rn(v0 - __half2float(h0));
    const __half l1 = __float2half_rn(v1 - __half2float(h1));
    hi = ((uint32_t)__half_as_ushort(h1) << 16) | __half_as_ushort(h0);
    lo = ((uint32_t)__half_as_ushort(l1) << 16) | __half_as_ushort(l0);
}

__device__ __forceinline__ void mma_h(float* d, const uint32_t* a, uint32_t b0, uint32_t b1)
{
    asm volatile(
        "mma.sync.aligned.m16n8k16.row.col.f32.f16.f16.f32 "
        "{%0,%1,%2,%3}, {%4,%5,%6,%7}, {%8,%9}, {%0,%1,%2,%3};"
        : "+f"(d[0]), "+f"(d[1]), "+f"(d[2]), "+f"(d[3])
        : "r"(a[0]), "r"(a[1]), "r"(a[2]), "r"(a[3]), "r"(b0), "r"(b1));
}

__device__ __forceinline__ void grid_barrier()
{
    __syncthreads();
    if (threadIdx.x == 0) {
        __threadfence();
        unsigned gen = g_bar_gen;
        if (atomicAdd(&g_bar_count, 1u) == (unsigned)(gridDim.x - 1)) {
            g_bar_count = 0;
            __threadfence();
            g_bar_gen = gen + 1;
            __threadfence();
        } else {
            while (g_bar_gen == gen) { __nanosleep(32); }
            __threadfence();
        }
    }
    __syncthreads();
}

__device__ __forceinline__ int memA(int pt) { return pt == 0 ? 0 : (pt == 1 ? 1 : pt + 2); }
__device__ __forceinline__ int memB(int pt) { return pt == 0 ? 2 : (pt == 1 ? 3 : pt + 10); }

extern __shared__ float sm[];

// stage one A-frag chunk into smem with the XOR-16 bank swizzle
__device__ __forceinline__ void copy_chunk(char* dst, const uint32_t* src_u32, int n_uint4, int tid)
{
    const uint4* src = (const uint4*)src_u32;
    for (int i = tid; i < n_uint4; i += BLK) {
        const uint4 v = __ldg(src + i);
        const int half = i & 1, lane2 = (i >> 1) & 31, km = i >> 6;
        *(uint4*)(dst + km * 1024 + lane2 * 32 + ((half * 16) ^ ((lane2 & 4) << 2))) = v;
    }
}

__global__ __launch_bounds__(BLK, 1) void lstm_h2(Params p, float* __restrict__ out,
                                                  int seq_off, int write_hT)
{
    const int tid = threadIdx.x;
    const int bid = blockIdx.x;
    const int lane = tid & 31;
    const int wid = tid >> 5;
    const int gtid = bid * BLK + tid;
    char* smc = (char*)sm;
    float* bias_sm = (float*)(smc + BIAS_B);
    float* ub = (float*)(smc + UBUF_B);
    char* astg = smc + ASTG_B;
    const uint32_t ho = lane * 32 + ((lane & 4) << 2);

    // ---- zero dynamic frag tables + c ----
    for (int i = gtid; i < 32 * 4 * 32 * 8; i += GRID * BLK) g_hp[i] = 0u;
    for (int i = gtid; i < 8 * 32 * 5 * 32 * 8; i += GRID * BLK) g_lp[i] = 0u;
    for (int i = gtid; i < B_DIM * H_DIM; i += GRID * BLK) g_c[i] = 0.0f;

    // ---- one-time: ext input A-frags (all t, split fp16) ----
    for (int idx = gtid; idx < T_DIM * 2048; idx += GRID * BLK) {
        const int t = idx >> 11;
        const int r = idx & 2047;
        const int b = r >> 5, q = (r & 31) * 2;
        float v0, v1;
        {
            const int qq = q;
            if (qq < 32) v0 = p.Y[((size_t)b * 32 + qq) * T_DIM + t];
            else if (qq < 56) { const int rr = qq - 32, xk = rr / 3, i2 = rr - 3 * xk;
                                v0 = p.x[xk][((size_t)b * 3 + i2) * T_DIM + t]; }
            else v0 = 0.0f;
        }
        {
            const int qq = q + 1;
            if (qq < 32) v1 = p.Y[((size_t)b * 32 + qq) * T_DIM + t];
            else if (qq < 56) { const int rr = qq - 32, xk = rr / 3, i2 = rr - 3 * xk;
                                v1 = p.x[xk][((size_t)b * 3 + i2) * T_DIM + t]; }
            else v1 = 0.0f;
        }
        uint32_t hi, lo; cvt_pair_h(v0, v1, hi, lo);
        const int lane2 = (b & 7) * 4 + ((q & 7) >> 1);
        const int slot = ((b >> 3) & 1) * 2 + ((q & 15) >> 3);
        const size_t base = ((((size_t)t * 4 + (q >> 4)) * 4 + (b >> 4)) * 32 + lane2) * 8 + slot;
        g_ep[base] = hi; g_ep[base + 4] = lo;
    }

    // ---- one-time: U pair-columns -> single-fp16 B-frags (smem) ----
    for (int e = tid; e < 80 * H_DIM; e += BLK) {
        const int s = e >> 9, j = e & 511;
        const int pq = bid * NPAIR + (s >> 1);
        const int pt = pq >> 9, c = pq & 511;
        const int m = (s & 1) ? memB(pt) : memA(pt);
        const float v = p.U[m][(size_t)j * H_DIM + c];
        const uint32_t off = (uint32_t)(s >> 3) * 8192u + (uint32_t)(j >> 4) * 256u
                           + (uint32_t)((s & 7) * 4 + ((j & 7) >> 1)) * 8u
                           + (uint32_t)((j & 15) >> 3) * 4u + (uint32_t)(j & 1) * 2u;
        *(unsigned short*)(smc + BF_B + off) = __half_as_ushort(__float2half_rn(v));
    }
    for (int e = tid; e < 2560; e += BLK) ((uint32_t*)(smc + BEXT_B))[e] = 0u;
    __syncthreads();
    for (int e = tid; e < 80 * 32; e += BLK) {
        const int s = e >> 5, i = e & 31;
        const int pq = bid * NPAIR + (s >> 1);
        const int pt = pq >> 9, c = pq & 511;
        const int m = (s & 1) ? memB(pt) : memA(pt);
        float v; int q;
        if (m < 4) { v = p.W[m][(size_t)i * H_DIM + c]; q = i; }
        else {
            if (i >= 3) continue;
            const int k = (m < 12) ? (m - 4) : (m - 12);
            const int xsel = (m < 12) ? ((k == 0) ? 0 : 1) : k;
            v = p.W[m][(size_t)i * H_DIM + c];
            q = 32 + xsel * 3 + i;
        }
        const uint32_t off = (uint32_t)(s >> 3) * 1024u + (uint32_t)(q >> 4) * 256u
                           + (uint32_t)((s & 7) * 4 + ((q & 7) >> 1)) * 8u
                           + (uint32_t)((q & 15) >> 3) * 4u + (uint32_t)(q & 1) * 2u;
        *(unsigned short*)(smc + BEXT_B + off) = __half_as_ushort(__float2half_rn(v));
    }
    for (int s = tid; s < 80; s += BLK) {
        const int pq = bid * NPAIR + (s >> 1);
        const int pt = pq >> 9, c = pq & 511;
        bias_sm[s] = p.bb[(s & 1) ? memB(pt) : memA(pt)][c];
    }
    // ---- one-time: W_a slice -> smem B-frags (per-CTA static) ----
    {
        const int Bhg_ = bid & 15;
        for (int e = tid; e < 16384; e += BLK) {
            const int j = e >> 5, h2 = e & 31;
            const float v = p.W_a[(size_t)j * H_DIM + Bhg_ * 32 + h2];
            const uint32_t off = (uint32_t)(j >> 4) * 1024u + (uint32_t)(h2 >> 4) * 512u
                               + (uint32_t)((h2 & 7) * 4 + ((j & 7) >> 1)) * 16u
                               + ((((uint32_t)h2 >> 3) & 1) * 2 + (((uint32_t)j & 15) >> 3)) * 4u
                               + (uint32_t)(j & 1) * 2u;
            *(unsigned short*)(smc + WAS_B + off) = __half_as_ushort(__float2half_rn(v));
        }
    }
    grid_barrier();

    // roles
    const int mi = wid & 3;
    const int nslot = wid >> 2;
    const int nt0 = (nslot == 0) ? 0 : (nslot == 1) ? 3 : (nslot == 2) ? 5 : 8;
    const int ntc = (nslot == 1 || nslot == 3) ? 2 : 3;
    const int g = lane >> 2, c4 = lane & 3;
    const int Bbg = bid >> 4, Bhg = bid & 15;

    for (int t = 0; t < T_DIM; t++) {
        // ================= PHASE A: staged A + smem B + fp16 2-product =================
        float d[3][4];
        #pragma unroll
        for (int tt = 0; tt < 3; tt++) { d[tt][0]=0.f; d[tt][1]=0.f; d[tt][2]=0.f; d[tt][3]=0.f; }

        copy_chunk(astg, g_hp, 2048, tid);
        __syncthreads();
        for (int c = 0; c <= 4; c++) {
            if (c < 4) {
                char* nbuf = astg + (((c + 1) & 1) ? 32768 : 0);
                if (c < 3) copy_chunk(nbuf, g_hp + (size_t)(c + 1) * 8192, 2048, tid);
                else       copy_chunk(nbuf, g_ep + (size_t)t * 4096, 1024, tid);
            }
            const char* bufp = astg + ((c & 1) ? 32768 : 0);
            const int nk = (c == 4) ? 4 : 8;
            for (int kl = 0; kl < nk; kl++) {
                const char* ap = bufp + (kl * 4 + mi) * 1024;
                const uint4 hv = *(const uint4*)(ap + ho);
                const uint4 lv = *(const uint4*)(ap + (ho ^ 16));
                const uint32_t ah[4] = {hv.x, hv.z, hv.y, hv.w};
                const uint32_t al[4] = {lv.x, lv.z, lv.y, lv.w};
                #pragma unroll
                for (int tt = 0; tt < 3; tt++) {
                    if (tt >= ntc) break;
                    const char* bp = (c == 4)
                        ? (smc + BEXT_B + (nt0 + tt) * 1024 + kl * 256)
                        : (smc + BF_B + (nt0 + tt) * 8192 + (c * 8 + kl) * 256);
                    const uint2 bv = *(const uint2*)(bp + lane * 8);
                    mma_h(d[tt], ah, bv.x, bv.y);
                    mma_h(d[tt], al, bv.x, bv.y);
                }
            }
            __syncthreads();
        }

        // epilogue: activations; fp32 l/f/o + packed fp16 l-frags
        #pragma unroll
        for (int tt = 0; tt < 3; tt++) {
            if (tt >= ntc) break;
            const int cl = (nt0 + tt) * 8 + c4 * 2;
            const int pq = bid * NPAIR + (cl >> 1);
            const int pt = pq >> 9, c = pq & 511;
            const float bA = bias_sm[cl], bB = bias_sm[cl + 1];
            const int b0 = mi * 16 + g, b1 = b0 + 8;
            const float sA0 = sigf(d[tt][0] + bA), sA1 = sigf(d[tt][2] + bA);
            if (pt == 1) {
                g_f[b0 * H_DIM + c] = sA0;
                g_f[b1 * H_DIM + c] = sA1;
                g_o[b0 * H_DIM + c] = sigf(d[tt][1] + bB);
                g_o[b1 * H_DIM + c] = sigf(d[tt][3] + bB);
            } else {
                const int kk = (pt == 0) ? 0 : pt - 1;
                const float lv0 = sA0 * tanhf(d[tt][1] + bB);
                const float lv1 = sA1 * tanhf(d[tt][3] + bB);
                g_l[((size_t)b0 * 9 + kk) * H_DIM + c] = lv0;
                g_l[((size_t)b1 * 9 + kk) * H_DIM + c] = lv1;
                const float n0 = __shfl_xor_sync(0xFFFFFFFFu, lv0, 1);
                const float n1 = __shfl_xor_sync(0xFFFFFFFFu, lv1, 1);
                const int ev = !(c4 & 1);
                const float pe0 = ev ? lv0 : n0, po0 = ev ? n0 : lv0;
                const float pe1 = ev ? lv1 : n1, po1 = ev ? n1 : lv1;
                const int cE = c & ~1;
                uint32_t hi0, lo0, hi1, lo1;
                cvt_pair_h(pe0, po0, hi0, lo0);
                cvt_pair_h(pe1, po1, hi1, lo1);
                const int lane2 = g * 4 + ((cE & 7) >> 1);
                const int slot = (kk & 1) * 2 + ((cE & 15) >> 3);
                const int mi2 = kk >> 1, j16 = cE >> 4;
                const int s = ev ? slot : (slot + 4);
                g_lp[((((size_t)(mi * 2) * 32 + j16) * 5 + mi2) * 32 + lane2) * 8 + s] = ev ? hi0 : lo0;
                g_lp[((((size_t)(mi * 2 + 1) * 32 + j16) * 5 + mi2) * 32 + lane2) * 8 + s] = ev ? hi1 : lo1;
            }
        }
        grid_barrier();

        // ================= PHASE B: LDG(A) + smem(Wa) + fp16 2-product =================
        if (wid < 10) {
            float d2[2][4];
            #pragma unroll
            for (int n8 = 0; n8 < 2; n8++) { d2[n8][0]=0.f; d2[n8][1]=0.f; d2[n8][2]=0.f; d2[n8][3]=0.f; }
            const int mi2w = wid >> 1, n16 = wid & 1;
            #pragma unroll 4
            for (int kl = 0; kl < 32; kl++) {
                const uint4* ap = (const uint4*)(g_lp + ((((size_t)Bbg * 32 + kl) * 5 + mi2w) * 32 + lane) * 8);
                const uint4 hv = __ldg(ap), lv = __ldg(ap + 1);
                const uint32_t ah[4] = {hv.x, hv.z, hv.y, hv.w};
                const uint32_t al[4] = {lv.x, lv.z, lv.y, lv.w};
                const uint4 wv = *(const uint4*)(smc + WAS_B + kl * 1024 + n16 * 512 + lane * 16);
                mma_h(d2[0], ah, wv.x, wv.y);
                mma_h(d2[0], al, wv.x, wv.y);
                mma_h(d2[1], ah, wv.z, wv.w);
                mma_h(d2[1], al, wv.z, wv.w);
            }
            const int r0 = mi2w * 16 + g, r1 = r0 + 8;
            #pragma unroll
            for (int n8 = 0; n8 < 2; n8++) {
                const int n0 = n16 * 16 + n8 * 8 + c4 * 2;
                ub[r0 * 32 + n0]     = d2[n8][0];
                ub[r0 * 32 + n0 + 1] = d2[n8][1];
                if (r1 < 72) {
                    ub[r1 * 32 + n0]     = d2[n8][2];
                    ub[r1 * 32 + n0 + 1] = d2[n8][3];
                }
            }
        }
        __syncthreads();

        // combine + packed fp16 h store
        if (tid < 256) {
            const int bl2 = tid >> 5, hl2 = tid & 31;
            const int b = Bbg * 8 + bl2, h = Bhg * 32 + hl2;
            const float c_old = g_c[b * H_DIM + h];
            const float ba = p.b_a[h];
            float uu[9], mx = -1e30f;
            #pragma unroll
            for (int k = 0; k < 9; k++) {
                const float u = ub[(k * 8 + bl2) * 32 + hl2];
                uu[k] = tanhf(u * c_old + ba);
                mx = fmaxf(mx, uu[k]);
            }
            float se = 0.0f, L = 0.0f;
            #pragma unroll
            for (int k = 0; k < 9; k++) {
                const float e = expf(uu[k] - mx);
                se += e;
                L += e * __ldcg(g_l + ((size_t)b * 9 + k) * H_DIM + h);
            }
            L /= se;
            const float cn = __ldcg(g_f + b * H_DIM + h) * c_old + L;
            const float hn = __ldcg(g_o + b * H_DIM + h) * tanhf(cn);
            g_c[b * H_DIM + h] = cn;

            const float nh = __shfl_xor_sync(0xFFFFFFFFu, hn, 1);
            const int ev = !(hl2 & 1);
            const float pe = ev ? hn : nh, po = ev ? nh : hn;
            uint32_t hi, lo;
            cvt_pair_h(pe, po, hi, lo);
            const int hE = h & ~1;
            const int lane2 = (b & 7) * 4 + ((hE & 7) >> 1);
            const int slot = ((b >> 3) & 1) * 2 + ((hE & 15) >> 3);
            const size_t dst = (((size_t)(hE >> 4) * 4 + (b >> 4)) * 32 + lane2) * 8;
            g_hp[dst + (ev ? slot : slot + 4)] = ev ? hi : lo;

            out[(size_t)seq_off + ((size_t)b * T_DIM + t) * H_DIM + h] = hn;
            if (write_hT && t == T_DIM - 1)
                out[(size_t)b * H_DIM + h] = hn;
        }
        grid_barrier();
    }
}

// ---------------------------------------------------------------------
extern "C" void kernel_launch(void* const* d_in, const int* in_sizes, int n_in,
                              void* d_out, int out_size)
{
    Params p;
    p.Y = (const float*)d_in[0];
    for (int j = 0; j < 8; j++) p.x[j] = (const float*)d_in[1 + j];
    const float* W_i = (const float*)d_in[9],  *U_i = (const float*)d_in[10], *b_i = (const float*)d_in[11];
    const float* W_f = (const float*)d_in[12], *U_f = (const float*)d_in[13], *b_f = (const float*)d_in[14];
    const float* W_c = (const float*)d_in[15], *U_c = (const float*)d_in[16], *b_c = (const float*)d_in[17];
    const float* W_o = (const float*)d_in[18], *U_o = (const float*)d_in[19], *b_o = (const float*)d_in[20];
    const float* W_i_x = (const float*)d_in[21], *U_i_x = (const float*)d_in[22], *b_i_x = (const float*)d_in[23];
    const float* W_c_x = (const float*)d_in[24], *U_c_x = (const float*)d_in[25], *b_c_x = (const float*)d_in[26];
    p.W_a = (const float*)d_in[27];
    p.b_a = (const float*)d_in[28];

    p.U[0] = U_i; p.U[1] = U_f; p.U[2] = U_c; p.U[3] = U_o;
    p.W[0] = W_i; p.W[1] = W_f; p.W[2] = W_c; p.W[3] = W_o;
    p.bb[0] = b_i; p.bb[1] = b_f; p.bb[2] = b_c; p.bb[3] = b_o;
    for (int k = 0; k < 8; k++) {
        p.U[4 + k]  = U_i_x + (size_t)k * H_DIM * H_DIM;
        p.U[12 + k] = U_c_x + (size_t)k * H_DIM * H_DIM;
        p.W[4 + k]  = W_i_x + (size_t)k * 3 * H_DIM;
        p.W[12 + k] = W_c_x + (size_t)k * 3 * H_DIM;
        p.bb[4 + k]  = b_i_x + (size_t)k * H_DIM;
        p.bb[12 + k] = b_c_x + (size_t)k * H_DIM;
    }

    float* out = (float*)d_out;
    const int full = B_DIM * H_DIM + B_DIM * T_DIM * H_DIM;
    const int seq_off = (out_size >= full) ? (B_DIM * H_DIM) : 0;
    const int write_hT = (seq_off != 0) ? 1 : 0;

    static int configured = 0;
    if (!configured) {
        cudaFuncSetAttribute(lstm_h2, cudaFuncAttributeMaxDynamicSharedMemorySize, SMEM_BYTES);
        configured = 1;
    }
    lstm_h2<<<GRID, BLK, SMEM_BYTES>>>(p, out, seq_off, write_hT);
}

// round 11
// speedup vs baseline: 10.8548x; 1.0122x over previous
#include <cuda_runtime.h>
#include <cuda_fp16.h>
#include <math.h>
#include <stdint.h>

#define B_DIM 64
#define T_DIM 1024
#define H_DIM 512
#define GRID  128
#define BLK   512
#define NPAIR 40

// ---- smem byte offsets ----
#define BF_B    0         // U-pair B-frags fp16: [nt10][kt32][lane32][8B] = 81920
#define BEXT_B  81920     // ext B-frags fp16: [nt10][ek4][lane32][8B] = 10240
#define WAS_B   92160     // W_a B-frags fp16: [kl32][n16 2][lane32][16B] = 32768
#define BIAS_B  124928    // 80 floats
#define UBUF_B  125248    // 72x32 fp32 = 9216
#define ASTG_B  134528    // A-stage double buffer 2x32KB
#define SMEM_BYTES 200064

// ---- device scratch ----
__device__ uint32_t g_hp[32 * 4 * 32 * 8];          // h A-frags fp16 split
__device__ uint32_t g_lp[8 * 32 * 5 * 32 * 8];      // l A-frags fp16 split
__device__ uint32_t g_ep[1024u * 4 * 4 * 32 * 8];   // ext A-frags fp16 split
__device__ float g_c[B_DIM * H_DIM];
__device__ float g_l[B_DIM * 9 * H_DIM];
__device__ float g_f[B_DIM * H_DIM];
__device__ float g_o[B_DIM * H_DIM];
__device__ unsigned g_bar_count = 0;
__device__ volatile unsigned g_bar_gen = 0;

struct Params {
    const float* U[20];
    const float* W[20];
    const float* bb[20];
    const float* Y;
    const float* x[8];
    const float* W_a;
    const float* b_a;
};

// ---- fast activations (MUFU) ----
__device__ __forceinline__ float tanh_fast(float z) {
    float r; asm("tanh.approx.f32 %0, %1;" : "=f"(r) : "f"(z)); return r;
}
__device__ __forceinline__ float exp_fast(float z) {
    float r; asm("ex2.approx.ftz.f32 %0, %1;" : "=f"(r) : "f"(z * 1.4426950408889634f));
    return r;
}
__device__ __forceinline__ float sig_fast(float z) {
    float ex; asm("ex2.approx.ftz.f32 %0, %1;" : "=f"(ex) : "f"(z * -1.4426950408889634f));
    float r;  asm("rcp.approx.ftz.f32 %0, %1;" : "=f"(r) : "f"(1.0f + ex));
    return r;
}

__device__ __forceinline__ void cvt_pair_h(float v0, float v1, uint32_t& hi, uint32_t& lo)
{
    const __half h0 = __float2half_rn(v0), h1 = __float2half_rn(v1);
    const __half l0 = __float2half_rn(v0 - __half2float(h0));
    const __half l1 = __float2half_rn(v1 - __half2float(h1));
    hi = ((uint32_t)__half_as_ushort(h1) << 16) | __half_as_ushort(h0);
    lo = ((uint32_t)__half_as_ushort(l1) << 16) | __half_as_ushort(l0);
}

__device__ __forceinline__ void mma_h(float* d, const uint32_t* a, uint32_t b0, uint32_t b1)
{
    asm volatile(
        "mma.sync.aligned.m16n8k16.row.col.f32.f16.f16.f32 "
        "{%0,%1,%2,%3}, {%4,%5,%6,%7}, {%8,%9}, {%0,%1,%2,%3};"
        : "+f"(d[0]), "+f"(d[1]), "+f"(d[2]), "+f"(d[3])
        : "r"(a[0]), "r"(a[1]), "r"(a[2]), "r"(a[3]), "r"(b0), "r"(b1));
}

__device__ __forceinline__ void grid_barrier()
{
    __syncthreads();
    if (threadIdx.x == 0) {
        __threadfence();
        unsigned gen = g_bar_gen;
        if (atomicAdd(&g_bar_count, 1u) == (unsigned)(gridDim.x - 1)) {
            g_bar_count = 0;
            __threadfence();
            g_bar_gen = gen + 1;
            __threadfence();
        } else {
            while (g_bar_gen == gen) { __nanosleep(32); }
            __threadfence();
        }
    }
    __syncthreads();
}

__device__ __forceinline__ int memA(int pt) { return pt == 0 ? 0 : (pt == 1 ? 1 : pt + 2); }
__device__ __forceinline__ int memB(int pt) { return pt == 0 ? 2 : (pt == 1 ? 3 : pt + 10); }

extern __shared__ float sm[];

__device__ __forceinline__ void copy_chunk(char* dst, const uint32_t* src_u32, int n_uint4, int tid)
{
    const uint4* src = (const uint4*)src_u32;
    for (int i = tid; i < n_uint4; i += BLK) {
        const uint4 v = __ldg(src + i);
        const int half = i & 1, lane2 = (i >> 1) & 31, km = i >> 6;
        *(uint4*)(dst + km * 1024 + lane2 * 32 + ((half * 16) ^ ((lane2 & 4) << 2))) = v;
    }
}

__global__ __launch_bounds__(BLK, 1) void lstm_h3(Params p, float* __restrict__ out,
                                                  int seq_off, int write_hT)
{
    const int tid = threadIdx.x;
    const int bid = blockIdx.x;
    const int lane = tid & 31;
    const int wid = tid >> 5;
    const int gtid = bid * BLK + tid;
    char* smc = (char*)sm;
    float* bias_sm = (float*)(smc + BIAS_B);
    float* ub = (float*)(smc + UBUF_B);
    char* astg = smc + ASTG_B;
    const uint32_t ho = lane * 32 + ((lane & 4) << 2);

    for (int i = gtid; i < 32 * 4 * 32 * 8; i += GRID * BLK) g_hp[i] = 0u;
    for (int i = gtid; i < 8 * 32 * 5 * 32 * 8; i += GRID * BLK) g_lp[i] = 0u;
    for (int i = gtid; i < B_DIM * H_DIM; i += GRID * BLK) g_c[i] = 0.0f;

    // ---- one-time: ext input A-frags (all t) ----
    for (int idx = gtid; idx < T_DIM * 2048; idx += GRID * BLK) {
        const int t = idx >> 11;
        const int r = idx & 2047;
        const int b = r >> 5, q = (r & 31) * 2;
        float v0, v1;
        {
            const int qq = q;
            if (qq < 32) v0 = p.Y[((size_t)b * 32 + qq) * T_DIM + t];
            else if (qq < 56) { const int rr = qq - 32, xk = rr / 3, i2 = rr - 3 * xk;
                                v0 = p.x[xk][((size_t)b * 3 + i2) * T_DIM + t]; }
            else v0 = 0.0f;
        }
        {
            const int qq = q + 1;
            if (qq < 32) v1 = p.Y[((size_t)b * 32 + qq) * T_DIM + t];
            else if (qq < 56) { const int rr = qq - 32, xk = rr / 3, i2 = rr - 3 * xk;
                                v1 = p.x[xk][((size_t)b * 3 + i2) * T_DIM + t]; }
            else v1 = 0.0f;
        }
        uint32_t hi, lo; cvt_pair_h(v0, v1, hi, lo);
        const int lane2 = (b & 7) * 4 + ((q & 7) >> 1);
        const int slot = ((b >> 3) & 1) * 2 + ((q & 15) >> 3);
        const size_t base = ((((size_t)t * 4 + (q >> 4)) * 4 + (b >> 4)) * 32 + lane2) * 8 + slot;
        g_ep[base] = hi; g_ep[base + 4] = lo;
    }

    // ---- one-time: U pair-columns -> fp16 B-frags (smem) ----
    for (int e = tid; e < 80 * H_DIM; e += BLK) {
        const int s = e >> 9, j = e & 511;
        const int pq = bid * NPAIR + (s >> 1);
        const int pt = pq >> 9, c = pq & 511;
        const int m = (s & 1) ? memB(pt) : memA(pt);
        const float v = p.U[m][(size_t)j * H_DIM + c];
        const uint32_t off = (uint32_t)(s >> 3) * 8192u + (uint32_t)(j >> 4) * 256u
                           + (uint32_t)((s & 7) * 4 + ((j & 7) >> 1)) * 8u
                           + (uint32_t)((j & 15) >> 3) * 4u + (uint32_t)(j & 1) * 2u;
        *(unsigned short*)(smc + BF_B + off) = __half_as_ushort(__float2half_rn(v));
    }
    for (int e = tid; e < 2560; e += BLK) ((uint32_t*)(smc + BEXT_B))[e] = 0u;
    __syncthreads();
    for (int e = tid; e < 80 * 32; e += BLK) {
        const int s = e >> 5, i = e & 31;
        const int pq = bid * NPAIR + (s >> 1);
        const int pt = pq >> 9, c = pq & 511;
        const int m = (s & 1) ? memB(pt) : memA(pt);
        float v; int q;
        if (m < 4) { v = p.W[m][(size_t)i * H_DIM + c]; q = i; }
        else {
            if (i >= 3) continue;
            const int k = (m < 12) ? (m - 4) : (m - 12);
            const int xsel = (m < 12) ? ((k == 0) ? 0 : 1) : k;
            v = p.W[m][(size_t)i * H_DIM + c];
            q = 32 + xsel * 3 + i;
        }
        const uint32_t off = (uint32_t)(s >> 3) * 1024u + (uint32_t)(q >> 4) * 256u
                           + (uint32_t)((s & 7) * 4 + ((q & 7) >> 1)) * 8u
                           + (uint32_t)((q & 15) >> 3) * 4u + (uint32_t)(q & 1) * 2u;
        *(unsigned short*)(smc + BEXT_B + off) = __half_as_ushort(__float2half_rn(v));
    }
    for (int s = tid; s < 80; s += BLK) {
        const int pq = bid * NPAIR + (s >> 1);
        const int pt = pq >> 9, c = pq & 511;
        bias_sm[s] = p.bb[(s & 1) ? memB(pt) : memA(pt)][c];
    }
    {
        const int Bhg_ = bid & 15;
        for (int e = tid; e < 16384; e += BLK) {
            const int j = e >> 5, h2 = e & 31;
            const float v = p.W_a[(size_t)j * H_DIM + Bhg_ * 32 + h2];
            const uint32_t off = (uint32_t)(j >> 4) * 1024u + (uint32_t)(h2 >> 4) * 512u
                               + (uint32_t)((h2 & 7) * 4 + ((j & 7) >> 1)) * 16u
                               + ((((uint32_t)h2 >> 3) & 1) * 2 + (((uint32_t)j & 15) >> 3)) * 4u
                               + (uint32_t)(j & 1) * 2u;
            *(unsigned short*)(smc + WAS_B + off) = __half_as_ushort(__float2half_rn(v));
        }
    }
    grid_barrier();

    // roles
    const int mi = wid & 3;
    const int nslot = wid >> 2;
    const int nt0 = (nslot == 0) ? 0 : (nslot == 1) ? 3 : (nslot == 2) ? 5 : 8;
    const int ntc = (nslot == 1 || nslot == 3) ? 2 : 3;
    const int g = lane >> 2, c4 = lane & 3;
    const int Bbg = bid >> 4, Bhg = bid & 15;

    for (int t = 0; t < T_DIM; t++) {
        // ================= PHASE A =================
        float d[3][4];
        #pragma unroll
        for (int tt = 0; tt < 3; tt++) { d[tt][0]=0.f; d[tt][1]=0.f; d[tt][2]=0.f; d[tt][3]=0.f; }

        copy_chunk(astg, g_hp, 2048, tid);
        __syncthreads();
        for (int c = 0; c <= 4; c++) {
            if (c < 4) {
                char* nbuf = astg + (((c + 1) & 1) ? 32768 : 0);
                if (c < 3) copy_chunk(nbuf, g_hp + (size_t)(c + 1) * 8192, 2048, tid);
                else       copy_chunk(nbuf, g_ep + (size_t)t * 4096, 1024, tid);
            }
            const char* bufp = astg + ((c & 1) ? 32768 : 0);
            const int nk = (c == 4) ? 4 : 8;
            for (int kl = 0; kl < nk; kl++) {
                const char* ap = bufp + (kl * 4 + mi) * 1024;
                const uint4 hv = *(const uint4*)(ap + ho);
                const uint4 lv = *(const uint4*)(ap + (ho ^ 16));
                const uint32_t ah[4] = {hv.x, hv.z, hv.y, hv.w};
                const uint32_t al[4] = {lv.x, lv.z, lv.y, lv.w};
                #pragma unroll
                for (int tt = 0; tt < 3; tt++) {
                    if (tt >= ntc) break;
                    const char* bp = (c == 4)
                        ? (smc + BEXT_B + (nt0 + tt) * 1024 + kl * 256)
                        : (smc + BF_B + (nt0 + tt) * 8192 + (c * 8 + kl) * 256);
                    const uint2 bv = *(const uint2*)(bp + lane * 8);
                    mma_h(d[tt], ah, bv.x, bv.y);
                    mma_h(d[tt], al, bv.x, bv.y);
                }
            }
            __syncthreads();
        }

        // epilogue: fast activations; fp32 l/f/o + packed fp16 l-frags
        #pragma unroll
        for (int tt = 0; tt < 3; tt++) {
            if (tt >= ntc) break;
            const int cl = (nt0 + tt) * 8 + c4 * 2;
            const int pq = bid * NPAIR + (cl >> 1);
            const int pt = pq >> 9, c = pq & 511;
            const float bA = bias_sm[cl], bB = bias_sm[cl + 1];
            const int b0 = mi * 16 + g, b1 = b0 + 8;
            const float sA0 = sig_fast(d[tt][0] + bA), sA1 = sig_fast(d[tt][2] + bA);
            if (pt == 1) {
                g_f[b0 * H_DIM + c] = sA0;
                g_f[b1 * H_DIM + c] = sA1;
                g_o[b0 * H_DIM + c] = sig_fast(d[tt][1] + bB);
                g_o[b1 * H_DIM + c] = sig_fast(d[tt][3] + bB);
            } else {
                const int kk = (pt == 0) ? 0 : pt - 1;
                const float lv0 = sA0 * tanh_fast(d[tt][1] + bB);
                const float lv1 = sA1 * tanh_fast(d[tt][3] + bB);
                g_l[((size_t)b0 * 9 + kk) * H_DIM + c] = lv0;
                g_l[((size_t)b1 * 9 + kk) * H_DIM + c] = lv1;
                const float n0 = __shfl_xor_sync(0xFFFFFFFFu, lv0, 1);
                const float n1 = __shfl_xor_sync(0xFFFFFFFFu, lv1, 1);
                const int ev = !(c4 & 1);
                const float pe0 = ev ? lv0 : n0, po0 = ev ? n0 : lv0;
                const float pe1 = ev ? lv1 : n1, po1 = ev ? n1 : lv1;
                const int cE = c & ~1;
                uint32_t hi0, lo0, hi1, lo1;
                cvt_pair_h(pe0, po0, hi0, lo0);
                cvt_pair_h(pe1, po1, hi1, lo1);
                const int lane2 = g * 4 + ((cE & 7) >> 1);
                const int slot = (kk & 1) * 2 + ((cE & 15) >> 3);
                const int mi2 = kk >> 1, j16 = cE >> 4;
                const int s = ev ? slot : (slot + 4);
                g_lp[((((size_t)(mi * 2) * 32 + j16) * 5 + mi2) * 32 + lane2) * 8 + s] = ev ? hi0 : lo0;
                g_lp[((((size_t)(mi * 2 + 1) * 32 + j16) * 5 + mi2) * 32 + lane2) * 8 + s] = ev ? hi1 : lo1;
            }
        }
        grid_barrier();

        // ================= PHASE B =================
        if (wid < 10) {
            float d2[2][4];
            #pragma unroll
            for (int n8 = 0; n8 < 2; n8++) { d2[n8][0]=0.f; d2[n8][1]=0.f; d2[n8][2]=0.f; d2[n8][3]=0.f; }
            const int mi2w = wid >> 1, n16 = wid & 1;
            #pragma unroll 4
            for (int kl = 0; kl < 32; kl++) {
                const uint4* ap = (const uint4*)(g_lp + ((((size_t)Bbg * 32 + kl) * 5 + mi2w) * 32 + lane) * 8);
                const uint4 hv = __ldg(ap), lv = __ldg(ap + 1);
                const uint32_t ah[4] = {hv.x, hv.z, hv.y, hv.w};
                const uint32_t al[4] = {lv.x, lv.z, lv.y, lv.w};
                const uint4 wv = *(const uint4*)(smc + WAS_B + kl * 1024 + n16 * 512 + lane * 16);
                mma_h(d2[0], ah, wv.x, wv.y);
                mma_h(d2[0], al, wv.x, wv.y);
                mma_h(d2[1], ah, wv.z, wv.w);
                mma_h(d2[1], al, wv.z, wv.w);
            }
            const int r0 = mi2w * 16 + g, r1 = r0 + 8;
            #pragma unroll
            for (int n8 = 0; n8 < 2; n8++) {
                const int n0 = n16 * 16 + n8 * 8 + c4 * 2;
                ub[r0 * 32 + n0]     = d2[n8][0];
                ub[r0 * 32 + n0 + 1] = d2[n8][1];
                if (r1 < 72) {
                    ub[r1 * 32 + n0]     = d2[n8][2];
                    ub[r1 * 32 + n0 + 1] = d2[n8][3];
                }
            }
        }
        __syncthreads();

        // combine + packed fp16 h store (fast activations)
        if (tid < 256) {
            const int bl2 = tid >> 5, hl2 = tid & 31;
            const int b = Bbg * 8 + bl2, h = Bhg * 32 + hl2;
            const float c_old = g_c[b * H_DIM + h];
            const float ba = p.b_a[h];
            float uu[9], mx = -1e30f;
            #pragma unroll
            for (int k = 0; k < 9; k++) {
                const float u = ub[(k * 8 + bl2) * 32 + hl2];
                uu[k] = tanh_fast(fmaf(u, c_old, ba));
                mx = fmaxf(mx, uu[k]);
            }
            float se = 0.0f, L = 0.0f;
            #pragma unroll
            for (int k = 0; k < 9; k++) {
                const float e = exp_fast(uu[k] - mx);
                se += e;
                L = fmaf(e, __ldcg(g_l + ((size_t)b * 9 + k) * H_DIM + h), L);
            }
            L /= se;
            const float cn = fmaf(__ldcg(g_f + b * H_DIM + h), c_old, L);
            const float hn = __ldcg(g_o + b * H_DIM + h) * tanh_fast(cn);
            g_c[b * H_DIM + h] = cn;

            const float nh = __shfl_xor_sync(0xFFFFFFFFu, hn, 1);
            const int ev = !(hl2 & 1);
            const float pe = ev ? hn : nh, po = ev ? nh : hn;
            uint32_t hi, lo;
            cvt_pair_h(pe, po, hi, lo);
            const int hE = h & ~1;
            const int lane2 = (b & 7) * 4 + ((hE & 7) >> 1);
            const int slot = ((b >> 3) & 1) * 2 + ((hE & 15) >> 3);
            const size_t dst = (((size_t)(hE >> 4) * 4 + (b >> 4)) * 32 + lane2) * 8;
            g_hp[dst + (ev ? slot : slot + 4)] = ev ? hi : lo;

            out[(size_t)seq_off + ((size_t)b * T_DIM + t) * H_DIM + h] = hn;
            if (write_hT && t == T_DIM - 1)
                out[(size_t)b * H_DIM + h] = hn;
        }
        grid_barrier();
    }
}

// ---------------------------------------------------------------------
extern "C" void kernel_launch(void* const* d_in, const int* in_sizes, int n_in,
                              void* d_out, int out_size)
{
    Params p;
    p.Y = (const float*)d_in[0];
    for (int j = 0; j < 8; j++) p.x[j] = (const float*)d_in[1 + j];
    const float* W_i = (const float*)d_in[9],  *U_i = (const float*)d_in[10], *b_i = (const float*)d_in[11];
    const float* W_f = (const float*)d_in[12], *U_f = (const float*)d_in[13], *b_f = (const float*)d_in[14];
    const float* W_c = (const float*)d_in[15], *U_c = (const float*)d_in[16], *b_c = (const float*)d_in[17];
    const float* W_o = (const float*)d_in[18], *U_o = (const float*)d_in[19], *b_o = (const float*)d_in[20];
    const float* W_i_x = (const float*)d_in[21], *U_i_x = (const float*)d_in[22], *b_i_x = (const float*)d_in[23];
    const float* W_c_x = (const float*)d_in[24], *U_c_x = (const float*)d_in[25], *b_c_x = (const float*)d_in[26];
    p.W_a = (const float*)d_in[27];
    p.b_a = (const float*)d_in[28];

    p.U[0] = U_i; p.U[1] = U_f; p.U[2] = U_c; p.U[3] = U_o;
    p.W[0] = W_i; p.W[1] = W_f; p.W[2] = W_c; p.W[3] = W_o;
    p.bb[0] = b_i; p.bb[1] = b_f; p.bb[2] = b_c; p.bb[3] = b_o;
    for (int k = 0; k < 8; k++) {
        p.U[4 + k]  = U_i_x + (size_t)k * H_DIM * H_DIM;
        p.U[12 + k] = U_c_x + (size_t)k * H_DIM * H_DIM;
        p.W[4 + k]  = W_i_x + (size_t)k * 3 * H_DIM;
        p.W[12 + k] = W_c_x + (size_t)k * 3 * H_DIM;
        p.bb[4 + k]  = b_i_x + (size_t)k * H_DIM;
        p.bb[12 + k] = b_c_x + (size_t)k * H_DIM;
    }

    float* out = (float*)d_out;
    const int full = B_DIM * H_DIM + B_DIM * T_DIM * H_DIM;
    const int seq_off = (out_size >= full) ? (B_DIM * H_DIM) : 0;
    const int write_hT = (seq_off != 0) ? 1 : 0;

    static int configured = 0;
    if (!configured) {
        cudaFuncSetAttribute(lstm_h3, cudaFuncAttributeMaxDynamicSharedMemorySize, SMEM_BYTES);
        configured = 1;
    }
    lstm_h3<<<GRID, BLK, SMEM_BYTES>>>(p, out, seq_off, write_hT);
}